// round 1
// baseline (speedup 1.0000x reference)
#include <cuda_runtime.h>
#include <math.h>
#include <stdint.h>

// Problem constants
#define Bn   256
#define Nn   199
#define Fin  256
#define Hh   8
#define Fout 256
#define HF   2048          // Hh * Fout
#define BN   (Bn * Nn)     // 50944
#define NPAD 208           // 13 * 16, padded N for K-loop
#define MW   7             // mask words per row (7*32 = 224 >= 199)
#define LDP  132           // Pt leading dim (floats): conflict-safe + 16B aligned rows
#define LDA  132           // As leading dim in gemm1

// Scratch (device globals — no runtime allocation allowed)
__device__ float    g_feats[(size_t)BN * HF];       // [b,n][h*256+d]  (417 MB)
__device__ float    g_eneigh[(size_t)Bn * Hh * Nn]; // [(b*8+h)*199 + n]
__device__ float    g_wneigh[Hh * Fin];             // W_h @ a_neigh
__device__ unsigned g_mbits[Nn * MW];               // adjacency bitmask rows

// ---------------------------------------------------------------------------
// Kernel P0: w_neigh[h,f] = sum_d W[h,f,d]*a_neigh[h,d]; adjacency bitmask
// ---------------------------------------------------------------------------
__global__ void prep_kernel(const float* __restrict__ W,
                            const float* __restrict__ a_neigh,
                            const int*   __restrict__ A) {
    int t = blockIdx.x * blockDim.x + threadIdx.x;
    int stride = gridDim.x * blockDim.x;
    for (int idx = t; idx < Hh * Fin; idx += stride) {
        int h = idx / Fin, f = idx % Fin;
        const float* wp = W + ((size_t)h * Fin + f) * Fout;
        const float* ap = a_neigh + h * Fout;
        float s = 0.f;
        for (int d = 0; d < Fout; d++) s += wp[d] * ap[d];
        g_wneigh[idx] = s;
    }
    for (int idx = t; idx < Nn * MW; idx += stride) {
        int i = idx / MW, c = idx % MW;
        unsigned m = 0u;
        for (int bb = 0; bb < 32; bb++) {
            int j = c * 32 + bb;
            if (j < Nn && A[i * Nn + j] != 0) m |= (1u << bb);
        }
        g_mbits[idx] = m;
    }
}

// ---------------------------------------------------------------------------
// Kernel P1: e_neigh[b,h,n] = X[b,n,:] . w_neigh[h,:]
// one warp per (b,n) row, loops 8 heads; grid = BN/8
// ---------------------------------------------------------------------------
__global__ void __launch_bounds__(256) eneigh_kernel(const float* __restrict__ X) {
    __shared__ float ws[Hh * Fin];
    const int tid = threadIdx.x;
    for (int i = tid; i < Hh * Fin; i += 256) ws[i] = g_wneigh[i];
    __syncthreads();

    const int warp = tid >> 5, lane = tid & 31;
    const int row = blockIdx.x * 8 + warp;   // < BN (exact: 6368*8)
    const float* xp = X + (size_t)row * Fin;
    float x[8];
    #pragma unroll
    for (int k = 0; k < 8; k++) x[k] = xp[lane + 32 * k];

    const int b = row / Nn, n = row % Nn;
    #pragma unroll
    for (int h = 0; h < Hh; h++) {
        float s = 0.f;
        #pragma unroll
        for (int k = 0; k < 8; k++) s = fmaf(x[k], ws[h * Fin + lane + 32 * k], s);
        #pragma unroll
        for (int o = 16; o > 0; o >>= 1) s += __shfl_xor_sync(0xffffffffu, s, o);
        if (lane == 0) g_eneigh[(size_t)(b * Hh + h) * Nn + n] = s;
    }
}

// ---------------------------------------------------------------------------
// Kernel G1: g_feats[m, col] = X[m,:] @ W'[:, col], col = h*256+d
// M=50944, N=2048, K=256. 128x128x16 tiles, 8x8 per thread, double-buffered.
// ---------------------------------------------------------------------------
__global__ void __launch_bounds__(256, 2) gemm1_kernel(const float* __restrict__ X,
                                                       const float* __restrict__ W) {
    __shared__ float As[2][16][LDA];
    __shared__ float Bs[2][16][128];
    const int tid = threadIdx.x;
    const int m0 = blockIdx.x * 128;
    const int ct = blockIdx.y;                   // 0..15 -> (h = ct/2, d0 = (ct&1)*128)
    const float* Wb = W + (size_t)(ct >> 1) * Fin * Fout + (ct & 1) * 128;

    const int am = tid >> 2, aq = tid & 3;       // A loader: rows am, am+64
    const int bk = tid >> 5, bq = tid & 31;      // B loader: k rows bk, bk+8

    float4 a0, a1, b0, b1;
    {
        a0 = *(const float4*)(X + (size_t)(m0 + am)      * Fin + aq * 4);
        a1 = *(const float4*)(X + (size_t)(m0 + am + 64) * Fin + aq * 4);
        b0 = *(const float4*)(Wb + (size_t)(bk)     * Fout + bq * 4);
        b1 = *(const float4*)(Wb + (size_t)(bk + 8) * Fout + bq * 4);
    }
    As[0][aq*4+0][am]    = a0.x; As[0][aq*4+1][am]    = a0.y;
    As[0][aq*4+2][am]    = a0.z; As[0][aq*4+3][am]    = a0.w;
    As[0][aq*4+0][am+64] = a1.x; As[0][aq*4+1][am+64] = a1.y;
    As[0][aq*4+2][am+64] = a1.z; As[0][aq*4+3][am+64] = a1.w;
    *(float4*)(&Bs[0][bk][bq*4])   = b0;
    *(float4*)(&Bs[0][bk+8][bq*4]) = b1;
    __syncthreads();

    const int tx = tid & 15, ty = tid >> 4;
    float acc[8][8];
    #pragma unroll
    for (int r = 0; r < 8; r++)
        #pragma unroll
        for (int c = 0; c < 8; c++) acc[r][c] = 0.f;

    int cur = 0;
    for (int kt = 0; kt < 16; kt++) {
        if (kt < 15) {
            const int k0 = (kt + 1) * 16;
            a0 = *(const float4*)(X + (size_t)(m0 + am)      * Fin + k0 + aq * 4);
            a1 = *(const float4*)(X + (size_t)(m0 + am + 64) * Fin + k0 + aq * 4);
            b0 = *(const float4*)(Wb + (size_t)(k0 + bk)     * Fout + bq * 4);
            b1 = *(const float4*)(Wb + (size_t)(k0 + bk + 8) * Fout + bq * 4);
        }
        #pragma unroll
        for (int kk = 0; kk < 16; kk++) {
            float af[8], bf[8];
            *(float4*)&af[0] = *(const float4*)&As[cur][kk][ty*8];
            *(float4*)&af[4] = *(const float4*)&As[cur][kk][ty*8 + 4];
            *(float4*)&bf[0] = *(const float4*)&Bs[cur][kk][tx*8];
            *(float4*)&bf[4] = *(const float4*)&Bs[cur][kk][tx*8 + 4];
            #pragma unroll
            for (int r = 0; r < 8; r++)
                #pragma unroll
                for (int c = 0; c < 8; c++)
                    acc[r][c] = fmaf(af[r], bf[c], acc[r][c]);
        }
        if (kt < 15) {
            const int nb = cur ^ 1;
            As[nb][aq*4+0][am]    = a0.x; As[nb][aq*4+1][am]    = a0.y;
            As[nb][aq*4+2][am]    = a0.z; As[nb][aq*4+3][am]    = a0.w;
            As[nb][aq*4+0][am+64] = a1.x; As[nb][aq*4+1][am+64] = a1.y;
            As[nb][aq*4+2][am+64] = a1.z; As[nb][aq*4+3][am+64] = a1.w;
            *(float4*)(&Bs[nb][bk][bq*4])   = b0;
            *(float4*)(&Bs[nb][bk+8][bq*4]) = b1;
            __syncthreads();
            cur = nb;
        }
    }

    const size_t colbase = (size_t)ct * 128 + tx * 8;
    #pragma unroll
    for (int r = 0; r < 8; r++) {
        float* op = g_feats + (size_t)(m0 + ty * 8 + r) * HF + colbase;
        float4 o;
        o.x = acc[r][0]; o.y = acc[r][1]; o.z = acc[r][2]; o.w = acc[r][3];
        *(float4*)op = o;
        o.x = acc[r][4]; o.y = acc[r][5]; o.z = acc[r][6]; o.w = acc[r][7];
        *(float4*)(op + 4) = o;
    }
}

// ---------------------------------------------------------------------------
// Kernel A2: per (b,h,row-tile): build P^T in smem (pre-softmax weights),
// then out[i,d] = (1/S_i) * sum_j P[i,j] * feats[b,j,h,d] + bias[h,d].
// Softmax trick: e_self cancels; p_ij = A_ij * exp(e_j - gmax) / S_i.
// ---------------------------------------------------------------------------
__global__ void __launch_bounds__(256) attn_kernel(const float* __restrict__ bias,
                                                   float* __restrict__ out) {
    extern __shared__ float sm[];
    float*    Pt   = sm;                       // [NPAD][LDP]  (k-major: Pt[j][i])
    float*    Vs   = Pt + NPAD * LDP;          // [2][16][128]
    float*    u    = Vs + 2 * 16 * 128;        // [NPAD]
    float*    Sinv = u + NPAD;                 // [128]
    float*    red  = Sinv + 128;               // [32]
    unsigned* mb   = (unsigned*)(red + 32);    // [Nn*MW]

    const int tid = threadIdx.x;
    const int bh  = blockIdx.x;                // b*8 + h
    const int b   = bh >> 3, h = bh & 7;
    const int i0  = blockIdx.y * 128;

    for (int i = tid; i < Nn * MW; i += 256) mb[i] = g_mbits[i];

    // global (per b,h) max of e_neigh, then u_j = exp(e_j - gmax)
    const float* ep = g_eneigh + (size_t)bh * Nn;
    float e = (tid < Nn) ? ep[tid] : -1e30f;
    float m = e;
    #pragma unroll
    for (int o = 16; o > 0; o >>= 1) m = fmaxf(m, __shfl_xor_sync(0xffffffffu, m, o));
    if ((tid & 31) == 0) red[tid >> 5] = m;
    __syncthreads();
    if (tid == 0) {
        float mm = red[0];
        for (int w = 1; w < 8; w++) mm = fmaxf(mm, red[w]);
        red[0] = mm;
    }
    __syncthreads();
    const float gmax = red[0];
    if (tid < NPAD) u[tid] = (tid < Nn) ? __expf(e - gmax) : 0.f;
    __syncthreads();

    // build P^T slice for rows [i0, i0+128) and row sums
    {
        const int warp = tid >> 5, lane = tid & 31;
        for (int il = warp; il < 128; il += 8) {
            const int ig = i0 + il;
            float s = 0.f;
            if (ig < Nn) {
                const unsigned* mrow = mb + ig * MW;
                for (int j = lane; j < NPAD; j += 32) {
                    float p = 0.f;
                    if (j < Nn && (mrow[j >> 5] & (1u << (j & 31)))) p = u[j];
                    Pt[j * LDP + il] = p;
                    s += p;
                }
            } else {
                for (int j = lane; j < NPAD; j += 32) Pt[j * LDP + il] = 0.f;
            }
            #pragma unroll
            for (int o = 16; o > 0; o >>= 1) s += __shfl_xor_sync(0xffffffffu, s, o);
            if (lane == 0) Sinv[il] = (ig < Nn) ? (1.f / s) : 0.f;
        }
    }
    __syncthreads();

    // GEMM: [128 rows] x [128 cols] over K = NPAD, feats streamed in 16-row tiles
    const int tx = tid & 15, ty = tid >> 4;
    const int vk = tid >> 5, vq = tid & 31;
    const float* fb = g_feats + (size_t)b * Nn * HF + h * Fout;

    for (int ct = 0; ct < 2; ct++) {
        const int d0 = ct * 128;
        float acc[8][8];
        #pragma unroll
        for (int r = 0; r < 8; r++)
            #pragma unroll
            for (int c = 0; c < 8; c++) acc[r][c] = 0.f;

        float4 v0, v1;
        {
            const int ja = vk, jb = vk + 8;  // always < Nn
            v0 = *(const float4*)(fb + (size_t)ja * HF + d0 + vq * 4);
            v1 = *(const float4*)(fb + (size_t)jb * HF + d0 + vq * 4);
        }
        *(float4*)&Vs[(0 * 16 + vk) * 128 + vq * 4]     = v0;
        *(float4*)&Vs[(0 * 16 + vk + 8) * 128 + vq * 4] = v1;
        __syncthreads();

        int cur = 0;
        for (int kt = 0; kt < 13; kt++) {
            if (kt < 12) {
                const int ja = (kt + 1) * 16 + vk, jb = ja + 8;
                v0 = (ja < Nn) ? *(const float4*)(fb + (size_t)ja * HF + d0 + vq * 4)
                               : make_float4(0.f, 0.f, 0.f, 0.f);
                v1 = (jb < Nn) ? *(const float4*)(fb + (size_t)jb * HF + d0 + vq * 4)
                               : make_float4(0.f, 0.f, 0.f, 0.f);
            }
            #pragma unroll
            for (int kk = 0; kk < 16; kk++) {
                const int k = kt * 16 + kk;
                float pf[8], vf[8];
                *(float4*)&pf[0] = *(const float4*)&Pt[k * LDP + ty * 8];
                *(float4*)&pf[4] = *(const float4*)&Pt[k * LDP + ty * 8 + 4];
                *(float4*)&vf[0] = *(const float4*)&Vs[(cur * 16 + kk) * 128 + tx * 8];
                *(float4*)&vf[4] = *(const float4*)&Vs[(cur * 16 + kk) * 128 + tx * 8 + 4];
                #pragma unroll
                for (int r = 0; r < 8; r++)
                    #pragma unroll
                    for (int c = 0; c < 8; c++)
                        acc[r][c] = fmaf(pf[r], vf[c], acc[r][c]);
            }
            if (kt < 12) {
                const int nb = cur ^ 1;
                *(float4*)&Vs[(nb * 16 + vk) * 128 + vq * 4]     = v0;
                *(float4*)&Vs[(nb * 16 + vk + 8) * 128 + vq * 4] = v1;
                __syncthreads();
                cur = nb;
            }
        }

        float bv[8];
        #pragma unroll
        for (int c = 0; c < 8; c++) bv[c] = bias[h * Fout + d0 + tx * 8 + c];
        #pragma unroll
        for (int r = 0; r < 8; r++) {
            const int ig = i0 + ty * 8 + r;
            if (ig < Nn) {
                const float si = Sinv[ty * 8 + r];
                float* op = out + (size_t)(b * Nn + ig) * HF + h * Fout + d0 + tx * 8;
                float4 o;
                o.x = fmaf(acc[r][0], si, bv[0]);
                o.y = fmaf(acc[r][1], si, bv[1]);
                o.z = fmaf(acc[r][2], si, bv[2]);
                o.w = fmaf(acc[r][3], si, bv[3]);
                *(float4*)op = o;
                o.x = fmaf(acc[r][4], si, bv[4]);
                o.y = fmaf(acc[r][5], si, bv[5]);
                o.z = fmaf(acc[r][6], si, bv[6]);
                o.w = fmaf(acc[r][7], si, bv[7]);
                *(float4*)(op + 4) = o;
            }
        }
        __syncthreads();  // protect Vs/acc reuse across ct
    }
}

// ---------------------------------------------------------------------------
extern "C" void kernel_launch(void* const* d_in, const int* in_sizes, int n_in,
                              void* d_out, int out_size) {
    const float* X       = (const float*)d_in[0];
    const int*   A       = (const int*)  d_in[1];
    const float* W       = (const float*)d_in[2];
    // d_in[3] = a_self: provably has no effect on the output (softmax row-constant)
    const float* a_neigh = (const float*)d_in[4];
    const float* bias    = (const float*)d_in[5];
    float* out = (float*)d_out;

    prep_kernel<<<16, 256>>>(W, a_neigh, A);
    eneigh_kernel<<<BN / 8, 256>>>(X);
    gemm1_kernel<<<dim3(398, 16), 256>>>(X, W);

    const size_t smem = (size_t)(NPAD * LDP + 2 * 16 * 128 + NPAD + 128 + 32) * 4
                        + (size_t)Nn * MW * 4;  // 133,252 B
    // Set once on the pre-capture correctness call; ignore errors thereafter.
    cudaFuncSetAttribute(attn_kernel, cudaFuncAttributeMaxDynamicSharedMemorySize,
                         (int)smem);
    attn_kernel<<<dim3(Bn * Hh, 2), 256, smem>>>(bias, out);
}

// round 4
// speedup vs baseline: 1.2694x; 1.2694x over previous
#include <cuda_runtime.h>
#include <cuda_bf16.h>
#include <math.h>
#include <stdint.h>

// Problem constants
#define Bn   256
#define Nn   199
#define Fin  256
#define Hh   8
#define Fout 256
#define HF   2048          // Hh * Fout
#define BN   (Bn * Nn)     // 50944
#define NPAD 208           // 13 * 16, padded N for attn K-loop
#define MW   7             // mask words per row
#define LDP  132           // Pt leading dim

// gemm1 (mma.sync) tiling — 3-segment split: [Ahi|Alo|Ahi] x [Bhi|Bhi|Blo]
#define KS   768           // 3 * 256
#define KCH  32            // K chunk per smem stage
#define NKC  (KS / KCH)    // 24
#define LDS  40            // smem row stride (bf16 elems): 80B, conflict-free ldmatrix

// ---------------------------------------------------------------------------
// Scratch (device globals — no runtime allocation allowed)
// ---------------------------------------------------------------------------
__device__ float         g_feats[(size_t)BN * HF];       // [m][h*256+d] fp32 (417 MB)
__device__ float         g_eneigh[(size_t)Bn * Hh * Nn];
__device__ float         g_wneigh[Hh * Fin];
__device__ unsigned      g_mbits[Nn * MW];
__device__ __nv_bfloat16 g_Xs[(size_t)BN * KS];          // X: [hi|lo|hi] (78 MB)
__device__ __nv_bfloat16 g_Wt[(size_t)HF * KS];          // W^T: [hi|hi|lo] (3 MB)

// ---------------------------------------------------------------------------
// mma.sync / ldmatrix helpers (sm_80+, valid on plain sm_100 target)
// ---------------------------------------------------------------------------
__device__ __forceinline__ void ldsm4(uint32_t& r0, uint32_t& r1, uint32_t& r2,
                                      uint32_t& r3, const void* p) {
    uint32_t a = (uint32_t)__cvta_generic_to_shared(p);
    asm volatile("ldmatrix.sync.aligned.m8n8.x4.shared.b16 {%0,%1,%2,%3}, [%4];"
                 : "=r"(r0), "=r"(r1), "=r"(r2), "=r"(r3) : "r"(a));
}
__device__ __forceinline__ void mma_bf16(float* c, const uint32_t* a,
                                         uint32_t b0, uint32_t b1) {
    asm volatile(
        "mma.sync.aligned.m16n8k16.row.col.f32.bf16.bf16.f32 "
        "{%0,%1,%2,%3}, {%4,%5,%6,%7}, {%8,%9}, {%0,%1,%2,%3};"
        : "+f"(c[0]), "+f"(c[1]), "+f"(c[2]), "+f"(c[3])
        : "r"(a[0]), "r"(a[1]), "r"(a[2]), "r"(a[3]), "r"(b0), "r"(b1));
}

// ---------------------------------------------------------------------------
// Kernel P0: w_neigh + adjacency bitmask
// ---------------------------------------------------------------------------
__global__ void prep_kernel(const float* __restrict__ W,
                            const float* __restrict__ a_neigh,
                            const int*   __restrict__ A) {
    int t = blockIdx.x * blockDim.x + threadIdx.x;
    int stride = gridDim.x * blockDim.x;
    for (int idx = t; idx < Hh * Fin; idx += stride) {
        int h = idx / Fin, f = idx % Fin;
        const float* wp = W + ((size_t)h * Fin + f) * Fout;
        const float* ap = a_neigh + h * Fout;
        float s = 0.f;
        for (int d = 0; d < Fout; d++) s += wp[d] * ap[d];
        g_wneigh[idx] = s;
    }
    for (int idx = t; idx < Nn * MW; idx += stride) {
        int i = idx / MW, c = idx % MW;
        unsigned m = 0u;
        for (int bb = 0; bb < 32; bb++) {
            int j = c * 32 + bb;
            if (j < Nn && A[i * Nn + j] != 0) m |= (1u << bb);
        }
        g_mbits[idx] = m;
    }
}

// ---------------------------------------------------------------------------
// Kernel P1: e_neigh[b,h,n] = X[b,n,:] . w_neigh[h,:]  (fp32 exact, feeds exp)
// ---------------------------------------------------------------------------
__global__ void __launch_bounds__(256) eneigh_kernel(const float* __restrict__ X) {
    __shared__ float ws[Hh * Fin];
    const int tid = threadIdx.x;
    for (int i = tid; i < Hh * Fin; i += 256) ws[i] = g_wneigh[i];
    __syncthreads();

    const int warp = tid >> 5, lane = tid & 31;
    const int row = blockIdx.x * 8 + warp;
    const float* xp = X + (size_t)row * Fin;
    float x[8];
    #pragma unroll
    for (int k = 0; k < 8; k++) x[k] = xp[lane + 32 * k];

    const int b = row / Nn, n = row % Nn;
    #pragma unroll
    for (int h = 0; h < Hh; h++) {
        float s = 0.f;
        #pragma unroll
        for (int k = 0; k < 8; k++) s = fmaf(x[k], ws[h * Fin + lane + 32 * k], s);
        #pragma unroll
        for (int o = 16; o > 0; o >>= 1) s += __shfl_xor_sync(0xffffffffu, s, o);
        if (lane == 0) g_eneigh[(size_t)(b * Hh + h) * Nn + n] = s;
    }
}

// ---------------------------------------------------------------------------
// Kernel S0: split X. Layout: [0:256)=hi, [256:512)=lo, [512:768)=hi copy.
// ---------------------------------------------------------------------------
__global__ void __launch_bounds__(256) split_x_kernel(const float* __restrict__ X) {
    const int idx = blockIdx.x * 256 + threadIdx.x;   // < BN*64
    const float4 x = ((const float4*)X)[idx];
    const int m = idx >> 6, f4 = idx & 63;
    float v[4] = {x.x, x.y, x.z, x.w};
    __nv_bfloat162 hp[2], lp[2];
    #pragma unroll
    for (int i = 0; i < 2; i++) {
        __nv_bfloat16 h0 = __float2bfloat16(v[2*i]);
        __nv_bfloat16 h1 = __float2bfloat16(v[2*i+1]);
        __nv_bfloat16 l0 = __float2bfloat16(v[2*i]   - __bfloat162float(h0));
        __nv_bfloat16 l1 = __float2bfloat16(v[2*i+1] - __bfloat162float(h1));
        hp[i].x = h0; hp[i].y = h1;
        lp[i].x = l0; lp[i].y = l1;
    }
    __nv_bfloat162* d0 = (__nv_bfloat162*)&g_Xs[(size_t)m * KS + f4 * 4];
    __nv_bfloat162* d1 = (__nv_bfloat162*)&g_Xs[(size_t)m * KS + 256 + f4 * 4];
    __nv_bfloat162* d2 = (__nv_bfloat162*)&g_Xs[(size_t)m * KS + 512 + f4 * 4];
    d0[0] = hp[0]; d0[1] = hp[1];
    d1[0] = lp[0]; d1[1] = lp[1];
    d2[0] = hp[0]; d2[1] = hp[1];
}

// ---------------------------------------------------------------------------
// Kernel S1: W^T split. Layout: [0:256)=hi, [256:512)=hi copy, [512:768)=lo.
// ---------------------------------------------------------------------------
__global__ void __launch_bounds__(256) split_w_kernel(const float* __restrict__ W) {
    const int idx = blockIdx.x * 256 + threadIdx.x;   // < HF*64
    const int col = idx >> 6, f4 = idx & 63;
    const int h = col >> 8, d = col & 255;
    #pragma unroll
    for (int i = 0; i < 4; i++) {
        int f = f4 * 4 + i;
        float v = W[((size_t)h * Fin + f) * Fout + d];
        __nv_bfloat16 hb = __float2bfloat16(v);
        __nv_bfloat16 lb = __float2bfloat16(v - __bfloat162float(hb));
        g_Wt[(size_t)col * KS + f]       = hb;
        g_Wt[(size_t)col * KS + 256 + f] = hb;
        g_Wt[(size_t)col * KS + 512 + f] = lb;
    }
}

// ---------------------------------------------------------------------------
// Kernel G1 (mma.sync): g_feats[m, col] = X[m,:] @ W'[:, col]  via 3-term split.
// CTA 128x128, 8 warps (2x4), warp tile 64x32, K=768 in 24 chunks of 32.
// ---------------------------------------------------------------------------
__global__ void __launch_bounds__(256) gemm1_mma() {
    __shared__ __align__(16) __nv_bfloat16 As[2][128][LDS];
    __shared__ __align__(16) __nv_bfloat16 Bs[2][128][LDS];

    const int tid  = threadIdx.x;
    const int lane = tid & 31, warp = tid >> 5;
    const int wm = warp >> 2, wn = warp & 3;          // warp grid 2x4
    const int m0 = blockIdx.x * 128, n0 = blockIdx.y * 128;

    const __nv_bfloat16* Ag = g_Xs + (size_t)m0 * KS;
    const __nv_bfloat16* Bg = g_Wt + (size_t)n0 * KS;

    const int r0l = tid >> 2, c0l = tid & 3;          // rows 0..63, 16B-vec col

    float acc[4][4][4];
    #pragma unroll
    for (int i = 0; i < 4; i++)
        #pragma unroll
        for (int j = 0; j < 4; j++)
            #pragma unroll
            for (int q = 0; q < 4; q++) acc[i][j][q] = 0.f;

    // prefetch chunk 0
    uint4 pa0, pa1, pb0, pb1;
    pa0 = *(const uint4*)(Ag + (size_t)r0l * KS + c0l * 8);
    pa1 = *(const uint4*)(Ag + (size_t)(r0l + 64) * KS + c0l * 8);
    pb0 = *(const uint4*)(Bg + (size_t)r0l * KS + c0l * 8);
    pb1 = *(const uint4*)(Bg + (size_t)(r0l + 64) * KS + c0l * 8);

    int buf = 0;
    *(uint4*)&As[0][r0l][c0l * 8]      = pa0;
    *(uint4*)&As[0][r0l + 64][c0l * 8] = pa1;
    *(uint4*)&Bs[0][r0l][c0l * 8]      = pb0;
    *(uint4*)&Bs[0][r0l + 64][c0l * 8] = pb1;
    __syncthreads();

    for (int c = 0; c < NKC; c++) {
        if (c + 1 < NKC) {   // issue next-chunk gmem loads before compute
            const int ko = (c + 1) * KCH;
            pa0 = *(const uint4*)(Ag + (size_t)r0l * KS + ko + c0l * 8);
            pa1 = *(const uint4*)(Ag + (size_t)(r0l + 64) * KS + ko + c0l * 8);
            pb0 = *(const uint4*)(Bg + (size_t)r0l * KS + ko + c0l * 8);
            pb1 = *(const uint4*)(Bg + (size_t)(r0l + 64) * KS + ko + c0l * 8);
        }

        #pragma unroll
        for (int ks = 0; ks < 2; ks++) {
            uint32_t ra[4][4], rb[2][4];
            #pragma unroll
            for (int am = 0; am < 4; am++)
                ldsm4(ra[am][0], ra[am][1], ra[am][2], ra[am][3],
                      &As[buf][wm * 64 + am * 16 + (lane & 15)]
                         [ks * 16 + (lane >> 4) * 8]);
            #pragma unroll
            for (int bn = 0; bn < 2; bn++)
                ldsm4(rb[bn][0], rb[bn][1], rb[bn][2], rb[bn][3],
                      &Bs[buf][wn * 32 + bn * 16 + (lane & 7) + ((lane >> 4) << 3)]
                         [ks * 16 + ((lane >> 3) & 1) * 8]);
            #pragma unroll
            for (int am = 0; am < 4; am++)
                #pragma unroll
                for (int an = 0; an < 4; an++)
                    mma_bf16(acc[am][an], ra[am],
                             rb[an >> 1][(an & 1) * 2], rb[an >> 1][(an & 1) * 2 + 1]);
        }

        if (c + 1 < NKC) {
            const int nb = buf ^ 1;
            *(uint4*)&As[nb][r0l][c0l * 8]      = pa0;
            *(uint4*)&As[nb][r0l + 64][c0l * 8] = pa1;
            *(uint4*)&Bs[nb][r0l][c0l * 8]      = pb0;
            *(uint4*)&Bs[nb][r0l + 64][c0l * 8] = pb1;
            __syncthreads();
            buf = nb;
        }
    }

    // epilogue: c-frag rows lane/4 (+8), cols 2*(lane&3)
    #pragma unroll
    for (int am = 0; am < 4; am++) {
        const int row = m0 + wm * 64 + am * 16 + (lane >> 2);
        #pragma unroll
        for (int an = 0; an < 4; an++) {
            const int col = n0 + wn * 32 + an * 8 + (lane & 3) * 2;
            float* p = g_feats + (size_t)row * HF + col;
            *(float2*)p = make_float2(acc[am][an][0], acc[am][an][1]);
            *(float2*)(p + 8 * HF) = make_float2(acc[am][an][2], acc[am][an][3]);
        }
    }
}

// ---------------------------------------------------------------------------
// Kernel A2: attention softmax + P@V (unchanged from R1)
// ---------------------------------------------------------------------------
__global__ void __launch_bounds__(256) attn_kernel(const float* __restrict__ bias,
                                                   float* __restrict__ out) {
    extern __shared__ float sm[];
    float*    Pt   = sm;
    float*    Vs   = Pt + NPAD * LDP;
    float*    u    = Vs + 2 * 16 * 128;
    float*    Sinv = u + NPAD;
    float*    red  = Sinv + 128;
    unsigned* mb   = (unsigned*)(red + 32);

    const int tid = threadIdx.x;
    const int bh  = blockIdx.x;
    const int b   = bh >> 3, h = bh & 7;
    const int i0  = blockIdx.y * 128;

    for (int i = tid; i < Nn * MW; i += 256) mb[i] = g_mbits[i];

    const float* ep = g_eneigh + (size_t)bh * Nn;
    float e = (tid < Nn) ? ep[tid] : -1e30f;
    float m = e;
    #pragma unroll
    for (int o = 16; o > 0; o >>= 1) m = fmaxf(m, __shfl_xor_sync(0xffffffffu, m, o));
    if ((tid & 31) == 0) red[tid >> 5] = m;
    __syncthreads();
    if (tid == 0) {
        float mm = red[0];
        for (int w = 1; w < 8; w++) mm = fmaxf(mm, red[w]);
        red[0] = mm;
    }
    __syncthreads();
    const float gmax = red[0];
    if (tid < NPAD) u[tid] = (tid < Nn) ? __expf(e - gmax) : 0.f;
    __syncthreads();

    {
        const int warp = tid >> 5, lane = tid & 31;
        for (int il = warp; il < 128; il += 8) {
            const int ig = i0 + il;
            float s = 0.f;
            if (ig < Nn) {
                const unsigned* mrow = mb + ig * MW;
                for (int j = lane; j < NPAD; j += 32) {
                    float p = 0.f;
                    if (j < Nn && (mrow[j >> 5] & (1u << (j & 31)))) p = u[j];
                    Pt[j * LDP + il] = p;
                    s += p;
                }
            } else {
                for (int j = lane; j < NPAD; j += 32) Pt[j * LDP + il] = 0.f;
            }
            #pragma unroll
            for (int o = 16; o > 0; o >>= 1) s += __shfl_xor_sync(0xffffffffu, s, o);
            if (lane == 0) Sinv[il] = (ig < Nn) ? (1.f / s) : 0.f;
        }
    }
    __syncthreads();

    const int tx = tid & 15, ty = tid >> 4;
    const int vk = tid >> 5, vq = tid & 31;
    const float* fb = g_feats + (size_t)b * Nn * HF + h * Fout;

    for (int ct = 0; ct < 2; ct++) {
        const int d0 = ct * 128;
        float acc[8][8];
        #pragma unroll
        for (int r = 0; r < 8; r++)
            #pragma unroll
            for (int c = 0; c < 8; c++) acc[r][c] = 0.f;

        float4 v0, v1;
        {
            const int ja = vk, jb = vk + 8;
            v0 = *(const float4*)(fb + (size_t)ja * HF + d0 + vq * 4);
            v1 = *(const float4*)(fb + (size_t)jb * HF + d0 + vq * 4);
        }
        *(float4*)&Vs[(0 * 16 + vk) * 128 + vq * 4]     = v0;
        *(float4*)&Vs[(0 * 16 + vk + 8) * 128 + vq * 4] = v1;
        __syncthreads();

        int cur = 0;
        for (int kt = 0; kt < 13; kt++) {
            if (kt < 12) {
                const int ja = (kt + 1) * 16 + vk, jb = ja + 8;
                v0 = (ja < Nn) ? *(const float4*)(fb + (size_t)ja * HF + d0 + vq * 4)
                               : make_float4(0.f, 0.f, 0.f, 0.f);
                v1 = (jb < Nn) ? *(const float4*)(fb + (size_t)jb * HF + d0 + vq * 4)
                               : make_float4(0.f, 0.f, 0.f, 0.f);
            }
            #pragma unroll
            for (int kk = 0; kk < 16; kk++) {
                const int k = kt * 16 + kk;
                float pf[8], vf[8];
                *(float4*)&pf[0] = *(const float4*)&Pt[k * LDP + ty * 8];
                *(float4*)&pf[4] = *(const float4*)&Pt[k * LDP + ty * 8 + 4];
                *(float4*)&vf[0] = *(const float4*)&Vs[(cur * 16 + kk) * 128 + tx * 8];
                *(float4*)&vf[4] = *(const float4*)&Vs[(cur * 16 + kk) * 128 + tx * 8 + 4];
                #pragma unroll
                for (int r = 0; r < 8; r++)
                    #pragma unroll
                    for (int c = 0; c < 8; c++)
                        acc[r][c] = fmaf(pf[r], vf[c], acc[r][c]);
            }
            if (kt < 12) {
                const int nb = cur ^ 1;
                *(float4*)&Vs[(nb * 16 + vk) * 128 + vq * 4]     = v0;
                *(float4*)&Vs[(nb * 16 + vk + 8) * 128 + vq * 4] = v1;
                __syncthreads();
                cur = nb;
            }
        }

        float bv[8];
        #pragma unroll
        for (int c = 0; c < 8; c++) bv[c] = bias[h * Fout + d0 + tx * 8 + c];
        #pragma unroll
        for (int r = 0; r < 8; r++) {
            const int ig = i0 + ty * 8 + r;
            if (ig < Nn) {
                const float si = Sinv[ty * 8 + r];
                float* op = out + (size_t)(b * Nn + ig) * HF + h * Fout + d0 + tx * 8;
                float4 o;
                o.x = fmaf(acc[r][0], si, bv[0]);
                o.y = fmaf(acc[r][1], si, bv[1]);
                o.z = fmaf(acc[r][2], si, bv[2]);
                o.w = fmaf(acc[r][3], si, bv[3]);
                *(float4*)op = o;
                o.x = fmaf(acc[r][4], si, bv[4]);
                o.y = fmaf(acc[r][5], si, bv[5]);
                o.z = fmaf(acc[r][6], si, bv[6]);
                o.w = fmaf(acc[r][7], si, bv[7]);
                *(float4*)(op + 4) = o;
            }
        }
        __syncthreads();
    }
}

// ---------------------------------------------------------------------------
extern "C" void kernel_launch(void* const* d_in, const int* in_sizes, int n_in,
                              void* d_out, int out_size) {
    const float* X       = (const float*)d_in[0];
    const int*   A       = (const int*)  d_in[1];
    const float* W       = (const float*)d_in[2];
    // d_in[3] = a_self: no effect on output (softmax row-constant cancels)
    const float* a_neigh = (const float*)d_in[4];
    const float* bias    = (const float*)d_in[5];
    float* out = (float*)d_out;

    prep_kernel<<<16, 256>>>(W, a_neigh, A);
    eneigh_kernel<<<BN / 8, 256>>>(X);
    split_x_kernel<<<BN * 64 / 256, 256>>>(X);
    split_w_kernel<<<HF * 64 / 256, 256>>>(W);

    gemm1_mma<<<dim3(BN / 128, HF / 128), 256>>>();

    const size_t smem = (size_t)(NPAD * LDP + 2 * 16 * 128 + NPAD + 128 + 32) * 4
                        + (size_t)Nn * MW * 4;  // 133,252 B
    cudaFuncSetAttribute(attn_kernel, cudaFuncAttributeMaxDynamicSharedMemorySize,
                         (int)smem);
    attn_kernel<<<dim3(Bn * Hh, 2), 256, smem>>>(bias, out);
}

// round 5
// speedup vs baseline: 1.4022x; 1.1046x over previous
#include <cuda_runtime.h>
#include <cuda_bf16.h>
#include <math.h>
#include <stdint.h>

// Problem constants
#define Bn   256
#define Nn   199
#define Fin  256
#define Hh   8
#define Fout 256
#define HF   2048          // Hh * Fout
#define BN   (Bn * Nn)     // 50944
#define MW   7             // mask words per row

// gemm1 (mma.sync) tiling — 3-segment split: [Ahi|Alo|Ahi] x [Bhi|Bhi|Blo]
#define KS   768           // 3 * 256
#define KCH  32            // K chunk per smem stage
#define NKC  (KS / KCH)    // 24
#define LDS  40            // gemm1 smem row stride (bf16): 80B, conflict-free

// attn (mma.sync) tiling
#define NJP   208          // padded j (13*16)
#define NPR   104          // j pairs
#define LDPH  216          // P smem row stride (bf16): 432B -> 12-bank row step
#define LDV   264          // V smem row stride (bf16): 528B -> 4-bank row step
#define NSTEP 39           // 3 segments * 13 k16-steps

// attn smem byte offsets (all 16B aligned)
#define OF_PH 0
#define OF_PL 55296        // 128*216*2
#define OF_VS 110592       // + 128*216*2
#define OF_UH 127488       // + 2*16*264*2
#define OF_UL 127904
#define OF_UF 128320
#define OF_SI 129152       // + 208*4
#define OF_RED 129664
#define OF_MB 129792
#define ATTN_SMEM 135424   // 129792 + 199*7*4 = 135364, rounded

// ---------------------------------------------------------------------------
// Scratch (device globals — no runtime allocation allowed)
// ---------------------------------------------------------------------------
__device__ __nv_bfloat16 g_fhi[(size_t)BN * HF];         // feats hi (209 MB)
__device__ __nv_bfloat16 g_flo[(size_t)BN * HF];         // feats lo (209 MB)
__device__ float         g_eneigh[(size_t)Bn * Hh * Nn];
__device__ float         g_wneigh[Hh * Fin];
__device__ unsigned      g_mbits[Nn * MW];
__device__ __nv_bfloat16 g_Xs[(size_t)BN * KS];          // X: [hi|lo|hi] (78 MB)
__device__ __nv_bfloat16 g_Wt[(size_t)HF * KS];          // W^T: [hi|hi|lo] (3 MB)

// ---------------------------------------------------------------------------
// mma.sync / ldmatrix helpers (sm_80+, valid on plain sm_100 target)
// ---------------------------------------------------------------------------
__device__ __forceinline__ void ldsm4(uint32_t& r0, uint32_t& r1, uint32_t& r2,
                                      uint32_t& r3, const void* p) {
    uint32_t a = (uint32_t)__cvta_generic_to_shared(p);
    asm volatile("ldmatrix.sync.aligned.m8n8.x4.shared.b16 {%0,%1,%2,%3}, [%4];"
                 : "=r"(r0), "=r"(r1), "=r"(r2), "=r"(r3) : "r"(a));
}
__device__ __forceinline__ void ldsm4t(uint32_t& r0, uint32_t& r1, uint32_t& r2,
                                       uint32_t& r3, const void* p) {
    uint32_t a = (uint32_t)__cvta_generic_to_shared(p);
    asm volatile("ldmatrix.sync.aligned.m8n8.x4.trans.shared.b16 {%0,%1,%2,%3}, [%4];"
                 : "=r"(r0), "=r"(r1), "=r"(r2), "=r"(r3) : "r"(a));
}
__device__ __forceinline__ void mma_bf16(float* c, const uint32_t* a,
                                         uint32_t b0, uint32_t b1) {
    asm volatile(
        "mma.sync.aligned.m16n8k16.row.col.f32.bf16.bf16.f32 "
        "{%0,%1,%2,%3}, {%4,%5,%6,%7}, {%8,%9}, {%0,%1,%2,%3};"
        : "+f"(c[0]), "+f"(c[1]), "+f"(c[2]), "+f"(c[3])
        : "r"(a[0]), "r"(a[1]), "r"(a[2]), "r"(a[3]), "r"(b0), "r"(b1));
}

// ---------------------------------------------------------------------------
// Kernel P0: w_neigh + adjacency bitmask
// ---------------------------------------------------------------------------
__global__ void prep_kernel(const float* __restrict__ W,
                            const float* __restrict__ a_neigh,
                            const int*   __restrict__ A) {
    int t = blockIdx.x * blockDim.x + threadIdx.x;
    int stride = gridDim.x * blockDim.x;
    for (int idx = t; idx < Hh * Fin; idx += stride) {
        int h = idx / Fin, f = idx % Fin;
        const float* wp = W + ((size_t)h * Fin + f) * Fout;
        const float* ap = a_neigh + h * Fout;
        float s = 0.f;
        for (int d = 0; d < Fout; d++) s += wp[d] * ap[d];
        g_wneigh[idx] = s;
    }
    for (int idx = t; idx < Nn * MW; idx += stride) {
        int i = idx / MW, c = idx % MW;
        unsigned m = 0u;
        for (int bb = 0; bb < 32; bb++) {
            int j = c * 32 + bb;
            if (j < Nn && A[i * Nn + j] != 0) m |= (1u << bb);
        }
        g_mbits[idx] = m;
    }
}

// ---------------------------------------------------------------------------
// Kernel P1: e_neigh[b,h,n] = X[b,n,:] . w_neigh[h,:]  (fp32 exact, feeds exp)
// ---------------------------------------------------------------------------
__global__ void __launch_bounds__(256) eneigh_kernel(const float* __restrict__ X) {
    __shared__ float ws[Hh * Fin];
    const int tid = threadIdx.x;
    for (int i = tid; i < Hh * Fin; i += 256) ws[i] = g_wneigh[i];
    __syncthreads();

    const int warp = tid >> 5, lane = tid & 31;
    const int row = blockIdx.x * 8 + warp;
    const float* xp = X + (size_t)row * Fin;
    float x[8];
    #pragma unroll
    for (int k = 0; k < 8; k++) x[k] = xp[lane + 32 * k];

    const int b = row / Nn, n = row % Nn;
    #pragma unroll
    for (int h = 0; h < Hh; h++) {
        float s = 0.f;
        #pragma unroll
        for (int k = 0; k < 8; k++) s = fmaf(x[k], ws[h * Fin + lane + 32 * k], s);
        #pragma unroll
        for (int o = 16; o > 0; o >>= 1) s += __shfl_xor_sync(0xffffffffu, s, o);
        if (lane == 0) g_eneigh[(size_t)(b * Hh + h) * Nn + n] = s;
    }
}

// ---------------------------------------------------------------------------
// Kernel S0: split X. Layout: [0:256)=hi, [256:512)=lo, [512:768)=hi copy.
// ---------------------------------------------------------------------------
__global__ void __launch_bounds__(256) split_x_kernel(const float* __restrict__ X) {
    const int idx = blockIdx.x * 256 + threadIdx.x;   // < BN*64
    const float4 x = ((const float4*)X)[idx];
    const int m = idx >> 6, f4 = idx & 63;
    float v[4] = {x.x, x.y, x.z, x.w};
    __nv_bfloat162 hp[2], lp[2];
    #pragma unroll
    for (int i = 0; i < 2; i++) {
        __nv_bfloat16 h0 = __float2bfloat16(v[2*i]);
        __nv_bfloat16 h1 = __float2bfloat16(v[2*i+1]);
        __nv_bfloat16 l0 = __float2bfloat16(v[2*i]   - __bfloat162float(h0));
        __nv_bfloat16 l1 = __float2bfloat16(v[2*i+1] - __bfloat162float(h1));
        hp[i].x = h0; hp[i].y = h1;
        lp[i].x = l0; lp[i].y = l1;
    }
    __nv_bfloat162* d0 = (__nv_bfloat162*)&g_Xs[(size_t)m * KS + f4 * 4];
    __nv_bfloat162* d1 = (__nv_bfloat162*)&g_Xs[(size_t)m * KS + 256 + f4 * 4];
    __nv_bfloat162* d2 = (__nv_bfloat162*)&g_Xs[(size_t)m * KS + 512 + f4 * 4];
    d0[0] = hp[0]; d0[1] = hp[1];
    d1[0] = lp[0]; d1[1] = lp[1];
    d2[0] = hp[0]; d2[1] = hp[1];
}

// ---------------------------------------------------------------------------
// Kernel S1: W^T split. Layout: [0:256)=hi, [256:512)=hi copy, [512:768)=lo.
// ---------------------------------------------------------------------------
__global__ void __launch_bounds__(256) split_w_kernel(const float* __restrict__ W) {
    const int idx = blockIdx.x * 256 + threadIdx.x;   // < HF*64
    const int col = idx >> 6, f4 = idx & 63;
    const int h = col >> 8, d = col & 255;
    #pragma unroll
    for (int i = 0; i < 4; i++) {
        int f = f4 * 4 + i;
        float v = W[((size_t)h * Fin + f) * Fout + d];
        __nv_bfloat16 hb = __float2bfloat16(v);
        __nv_bfloat16 lb = __float2bfloat16(v - __bfloat162float(hb));
        g_Wt[(size_t)col * KS + f]       = hb;
        g_Wt[(size_t)col * KS + 256 + f] = hb;
        g_Wt[(size_t)col * KS + 512 + f] = lb;
    }
}

// ---------------------------------------------------------------------------
// Kernel G1 (mma.sync): feats = X @ W' via 3-term split; epilogue writes
// bf16 hi/lo pair tensors for the attention stage.
// ---------------------------------------------------------------------------
__global__ void __launch_bounds__(256) gemm1_mma() {
    __shared__ __align__(16) __nv_bfloat16 As[2][128][LDS];
    __shared__ __align__(16) __nv_bfloat16 Bs[2][128][LDS];

    const int tid  = threadIdx.x;
    const int lane = tid & 31, warp = tid >> 5;
    const int wm = warp >> 2, wn = warp & 3;          // warp grid 2x4
    const int m0 = blockIdx.x * 128, n0 = blockIdx.y * 128;

    const __nv_bfloat16* Ag = g_Xs + (size_t)m0 * KS;
    const __nv_bfloat16* Bg = g_Wt + (size_t)n0 * KS;

    const int r0l = tid >> 2, c0l = tid & 3;          // rows 0..63, 16B-vec col

    float acc[4][4][4];
    #pragma unroll
    for (int i = 0; i < 4; i++)
        #pragma unroll
        for (int j = 0; j < 4; j++)
            #pragma unroll
            for (int q = 0; q < 4; q++) acc[i][j][q] = 0.f;

    uint4 pa0, pa1, pb0, pb1;
    pa0 = *(const uint4*)(Ag + (size_t)r0l * KS + c0l * 8);
    pa1 = *(const uint4*)(Ag + (size_t)(r0l + 64) * KS + c0l * 8);
    pb0 = *(const uint4*)(Bg + (size_t)r0l * KS + c0l * 8);
    pb1 = *(const uint4*)(Bg + (size_t)(r0l + 64) * KS + c0l * 8);

    int buf = 0;
    *(uint4*)&As[0][r0l][c0l * 8]      = pa0;
    *(uint4*)&As[0][r0l + 64][c0l * 8] = pa1;
    *(uint4*)&Bs[0][r0l][c0l * 8]      = pb0;
    *(uint4*)&Bs[0][r0l + 64][c0l * 8] = pb1;
    __syncthreads();

    for (int c = 0; c < NKC; c++) {
        if (c + 1 < NKC) {
            const int ko = (c + 1) * KCH;
            pa0 = *(const uint4*)(Ag + (size_t)r0l * KS + ko + c0l * 8);
            pa1 = *(const uint4*)(Ag + (size_t)(r0l + 64) * KS + ko + c0l * 8);
            pb0 = *(const uint4*)(Bg + (size_t)r0l * KS + ko + c0l * 8);
            pb1 = *(const uint4*)(Bg + (size_t)(r0l + 64) * KS + ko + c0l * 8);
        }

        #pragma unroll
        for (int ks = 0; ks < 2; ks++) {
            uint32_t ra[4][4], rb[2][4];
            #pragma unroll
            for (int am = 0; am < 4; am++)
                ldsm4(ra[am][0], ra[am][1], ra[am][2], ra[am][3],
                      &As[buf][wm * 64 + am * 16 + (lane & 15)]
                         [ks * 16 + (lane >> 4) * 8]);
            #pragma unroll
            for (int bn = 0; bn < 2; bn++)
                ldsm4(rb[bn][0], rb[bn][1], rb[bn][2], rb[bn][3],
                      &Bs[buf][wn * 32 + bn * 16 + (lane & 7) + ((lane >> 4) << 3)]
                         [ks * 16 + ((lane >> 3) & 1) * 8]);
            #pragma unroll
            for (int am = 0; am < 4; am++)
                #pragma unroll
                for (int an = 0; an < 4; an++)
                    mma_bf16(acc[am][an], ra[am],
                             rb[an >> 1][(an & 1) * 2], rb[an >> 1][(an & 1) * 2 + 1]);
        }

        if (c + 1 < NKC) {
            const int nb = buf ^ 1;
            *(uint4*)&As[nb][r0l][c0l * 8]      = pa0;
            *(uint4*)&As[nb][r0l + 64][c0l * 8] = pa1;
            *(uint4*)&Bs[nb][r0l][c0l * 8]      = pb0;
            *(uint4*)&Bs[nb][r0l + 64][c0l * 8] = pb1;
            __syncthreads();
            buf = nb;
        }
    }

    // epilogue: split each fp32 result into bf16 hi + lo, write pair tensors
    #pragma unroll
    for (int am = 0; am < 4; am++) {
        const int row = m0 + wm * 64 + am * 16 + (lane >> 2);
        #pragma unroll
        for (int an = 0; an < 4; an++) {
            const int col = n0 + wn * 32 + an * 8 + (lane & 3) * 2;
            #pragma unroll
            for (int rr = 0; rr < 2; rr++) {
                const size_t off = (size_t)(row + rr * 8) * HF + col;
                float f0 = acc[am][an][rr * 2], f1 = acc[am][an][rr * 2 + 1];
                __nv_bfloat16 h0 = __float2bfloat16(f0);
                __nv_bfloat16 h1 = __float2bfloat16(f1);
                __nv_bfloat162 hp, lp;
                hp.x = h0; hp.y = h1;
                lp.x = __float2bfloat16(f0 - __bfloat162float(h0));
                lp.y = __float2bfloat16(f1 - __bfloat162float(h1));
                *(__nv_bfloat162*)(g_fhi + off) = hp;
                *(__nv_bfloat162*)(g_flo + off) = lp;
            }
        }
    }
}

// ---------------------------------------------------------------------------
// Kernel A2 (mma.sync): masked softmax + P@V via 3-term bf16 split.
// Segments: (P_hi,V_hi), (P_lo,V_hi), (P_hi,V_lo). K = 3*208, N = 256.
// ---------------------------------------------------------------------------
__global__ void __launch_bounds__(256) attn_mma(const float* __restrict__ bias,
                                                float* __restrict__ out) {
    extern __shared__ char sm[];
    __nv_bfloat16* Ph = (__nv_bfloat16*)(sm + OF_PH);   // [128][LDPH]
    __nv_bfloat16* Pl = (__nv_bfloat16*)(sm + OF_PL);   // [128][LDPH]
    __nv_bfloat16* Vs = (__nv_bfloat16*)(sm + OF_VS);   // [2][16][LDV]
    __nv_bfloat16* uh = (__nv_bfloat16*)(sm + OF_UH);   // [NJP]
    __nv_bfloat16* ul = (__nv_bfloat16*)(sm + OF_UL);   // [NJP]
    float*         uf = (float*)(sm + OF_UF);           // [NJP]
    float*       Sinv = (float*)(sm + OF_SI);           // [128]
    float*        red = (float*)(sm + OF_RED);          // [32]
    unsigned*      mb = (unsigned*)(sm + OF_MB);        // [Nn*MW]

    const int tid = threadIdx.x, lane = tid & 31, warp = tid >> 5;
    const int bh = blockIdx.x, b = bh >> 3, h = bh & 7;
    const int i0 = blockIdx.y * 128;
    const int wm = warp >> 2, wn = warp & 3;            // warp grid 2x4 (64i x 64d)

    for (int i = tid; i < Nn * MW; i += 256) mb[i] = g_mbits[i];

    // softmax weights u_j = exp(e_j - gmax), split into bf16 hi/lo
    const float* ep = g_eneigh + (size_t)bh * Nn;
    float e = (tid < Nn) ? ep[tid] : -1e30f;
    float m = e;
    #pragma unroll
    for (int o = 16; o > 0; o >>= 1) m = fmaxf(m, __shfl_xor_sync(0xffffffffu, m, o));
    if (lane == 0) red[warp] = m;
    __syncthreads();
    if (tid == 0) {
        float mm = red[0];
        for (int w = 1; w < 8; w++) mm = fmaxf(mm, red[w]);
        red[0] = mm;
    }
    __syncthreads();
    const float gmax = red[0];
    if (tid < NJP) {
        float uu = (tid < Nn) ? __expf(e - gmax) : 0.f;
        uf[tid] = uu;
        __nv_bfloat16 hb = __float2bfloat16(uu);
        uh[tid] = hb;
        ul[tid] = __float2bfloat16(uu - __bfloat162float(hb));
    }
    __syncthreads();

    // build P_hi / P_lo tiles: packed j-pair writes, mask via bitwise AND
    for (int t = tid; t < 128 * NPR; t += 256) {
        const int i = t / NPR, jp = t - i * NPR;
        const int ig = i0 + i;
        uint32_t mw_ = 0u;
        if (ig < Nn) {
            const unsigned* mrow = mb + ig * MW;
            const int j0 = jp * 2, j1 = j0 + 1;
            // bits >= Nn are 0 in g_mbits, so no j<Nn guard needed (j1 <= 207 < 224)
            if ((mrow[j0 >> 5] >> (j0 & 31)) & 1u) mw_ |= 0x0000FFFFu;
            if ((mrow[j1 >> 5] >> (j1 & 31)) & 1u) mw_ |= 0xFFFF0000u;
        }
        const uint32_t uhp = ((const uint32_t*)uh)[jp];
        const uint32_t ulp = ((const uint32_t*)ul)[jp];
        ((uint32_t*)(Ph + (size_t)i * LDPH))[jp] = uhp & mw_;
        ((uint32_t*)(Pl + (size_t)i * LDPH))[jp] = ulp & mw_;
    }

    // row sums -> Sinv
    for (int il = warp; il < 128; il += 8) {
        const int ig = i0 + il;
        float s = 0.f;
        if (ig < Nn) {
            const unsigned* mrow = mb + ig * MW;
            for (int j = lane; j < Nn; j += 32)
                if (mrow[j >> 5] & (1u << (j & 31))) s += uf[j];
        }
        #pragma unroll
        for (int o = 16; o > 0; o >>= 1) s += __shfl_xor_sync(0xffffffffu, s, o);
        if (lane == 0) Sinv[il] = (ig < Nn) ? (1.f / s) : 0.f;
    }
    __syncthreads();

    // K-loop: 39 steps of k=16 (3 segments x 13), V double-buffered
    const __nv_bfloat16* fbh = g_fhi + (size_t)b * Nn * HF + h * Fout;
    const __nv_bfloat16* fbl = g_flo + (size_t)b * Nn * HF + h * Fout;

    float acc[4][8][4];
    #pragma unroll
    for (int i = 0; i < 4; i++)
        #pragma unroll
        for (int j = 0; j < 8; j++)
            #pragma unroll
            for (int q = 0; q < 4; q++) acc[i][j][q] = 0.f;

    const int vr = tid >> 4, vc = tid & 15;   // V loader: row, two 16B cols
    uint4 pv0, pv1;
    {   // chunk 0 (seg 0 = hi, j0 = 0); vr <= 15 < Nn always
        pv0 = *(const uint4*)(fbh + (size_t)vr * HF + vc * 8);
        pv1 = *(const uint4*)(fbh + (size_t)vr * HF + (vc + 16) * 8);
    }
    *(uint4*)&Vs[(0 * 16 + vr) * LDV + vc * 8]        = pv0;
    *(uint4*)&Vs[(0 * 16 + vr) * LDV + (vc + 16) * 8] = pv1;
    __syncthreads();

    int buf = 0;
    for (int step = 0; step < NSTEP; step++) {
        if (step + 1 < NSTEP) {
            const int s1 = (step + 1) / 13;
            const int j = ((step + 1) % 13) * 16 + vr;
            const __nv_bfloat16* src = (s1 < 2) ? fbh : fbl;
            if (j < Nn) {
                pv0 = *(const uint4*)(src + (size_t)j * HF + vc * 8);
                pv1 = *(const uint4*)(src + (size_t)j * HF + (vc + 16) * 8);
            } else {
                pv0 = make_uint4(0, 0, 0, 0);
                pv1 = make_uint4(0, 0, 0, 0);
            }
        }

        const int s = step / 13;
        const int kc = (step % 13) * 16;
        const __nv_bfloat16* Pt_ = (s == 1) ? Pl : Ph;

        uint32_t ra[4][4], rb[4][4];
        #pragma unroll
        for (int am = 0; am < 4; am++)
            ldsm4(ra[am][0], ra[am][1], ra[am][2], ra[am][3],
                  Pt_ + (size_t)(wm * 64 + am * 16 + (lane & 15)) * LDPH
                      + kc + (lane >> 4) * 8);
        #pragma unroll
        for (int q = 0; q < 4; q++)
            ldsm4t(rb[q][0], rb[q][1], rb[q][2], rb[q][3],
                   &Vs[(buf * 16 + (lane & 15)) * LDV
                       + wn * 64 + q * 16 + ((lane >> 4) << 3)]);
        #pragma unroll
        for (int am = 0; am < 4; am++)
            #pragma unroll
            for (int an = 0; an < 8; an++)
                mma_bf16(acc[am][an], ra[am],
                         rb[an >> 1][(an & 1) * 2], rb[an >> 1][(an & 1) * 2 + 1]);

        if (step + 1 < NSTEP) {
            const int nb = buf ^ 1;
            *(uint4*)&Vs[(nb * 16 + vr) * LDV + vc * 8]        = pv0;
            *(uint4*)&Vs[(nb * 16 + vr) * LDV + (vc + 16) * 8] = pv1;
            __syncthreads();
            buf = nb;
        }
    }

    // epilogue: scale by Sinv, add bias, store fp32
    #pragma unroll
    for (int am = 0; am < 4; am++) {
        const int il = wm * 64 + am * 16 + (lane >> 2);
        const int ig0 = i0 + il, ig1 = ig0 + 8;
        const float si0 = Sinv[il], si1 = Sinv[il + 8];
        #pragma unroll
        for (int an = 0; an < 8; an++) {
            const int d = wn * 64 + an * 8 + (lane & 3) * 2;
            const float bv0 = bias[h * Fout + d];
            const float bv1 = bias[h * Fout + d + 1];
            if (ig0 < Nn) {
                float* p = out + (size_t)(b * Nn + ig0) * HF + h * Fout + d;
                *(float2*)p = make_float2(fmaf(acc[am][an][0], si0, bv0),
                                          fmaf(acc[am][an][1], si0, bv1));
            }
            if (ig1 < Nn) {
                float* p = out + (size_t)(b * Nn + ig1) * HF + h * Fout + d;
                *(float2*)p = make_float2(fmaf(acc[am][an][2], si1, bv0),
                                          fmaf(acc[am][an][3], si1, bv1));
            }
        }
    }
}

// ---------------------------------------------------------------------------
extern "C" void kernel_launch(void* const* d_in, const int* in_sizes, int n_in,
                              void* d_out, int out_size) {
    const float* X       = (const float*)d_in[0];
    const int*   A       = (const int*)  d_in[1];
    const float* W       = (const float*)d_in[2];
    // d_in[3] = a_self: no effect on output (softmax row-constant cancels)
    const float* a_neigh = (const float*)d_in[4];
    const float* bias    = (const float*)d_in[5];
    float* out = (float*)d_out;

    prep_kernel<<<16, 256>>>(W, a_neigh, A);
    eneigh_kernel<<<BN / 8, 256>>>(X);
    split_x_kernel<<<BN * 64 / 256, 256>>>(X);
    split_w_kernel<<<HF * 64 / 256, 256>>>(W);

    gemm1_mma<<<dim3(BN / 128, HF / 128), 256>>>();

    cudaFuncSetAttribute(attn_mma, cudaFuncAttributeMaxDynamicSharedMemorySize,
                         ATTN_SMEM);
    attn_mma<<<dim3(Bn * Hh, 2), 256, ATTN_SMEM>>>(bias, out);
}

// round 6
// speedup vs baseline: 1.9555x; 1.3946x over previous
#include <cuda_runtime.h>
#include <cuda_bf16.h>
#include <cuda_fp16.h>
#include <math.h>
#include <stdint.h>

// Problem constants
#define Bn   256
#define Nn   199
#define Fin  256
#define Hh   8
#define Fout 256
#define HF   2048          // Hh * Fout
#define BN   (Bn * Nn)     // 50944
#define MW   7             // mask words per row

// gemm1 (mma.sync) tiling — 3-segment split: [Ahi|Alo|Ahi] x [Bhi|Bhi|Blo]
#define KS   768           // 3 * 256
#define KCH  32            // K chunk per smem stage
#define NKC  (KS / KCH)    // 24
#define LDS  40            // gemm1 smem row stride (bf16): 80B, conflict-free
#define GSTG 4             // cp.async stages
#define G1_SMEM (2 * GSTG * 128 * LDS * 2)   // 81920 B

// attn (mma.sync) tiling — P fp16 exact, V fp16 hi/lo: 2 segments
#define NJP   208          // padded j (13*16)
#define NPR   104          // j pairs
#define LDPH  216          // P smem row stride (halfs): 432B -> conflict-free
#define LDV   264          // V smem row stride (halfs): 528B -> conflict-free
#define NSTEP 26           // 2 segments * 13 k16-steps
#define VSTG  4

// attn smem byte offsets (all 16B aligned)
#define OF_PH 0
#define OF_VS 55296        // 128*216*2
#define OF_UH 89088        // + 4*16*264*2
#define OF_SI 89504        // + 208*2
#define OF_RED 90016
#define OF_MB 90144
#define ATTN_SMEM 95744    // 90144 + 199*7*4 = 95716, rounded

// ---------------------------------------------------------------------------
// Scratch (device globals — no runtime allocation allowed)
// ---------------------------------------------------------------------------
__device__ __half        g_fhi[(size_t)BN * HF];         // feats hi (209 MB)
__device__ __half        g_flo[(size_t)BN * HF];         // feats lo (209 MB)
__device__ float         g_eneigh[(size_t)Bn * Hh * Nn];
__device__ float         g_wneigh[Hh * Fin];
__device__ unsigned      g_mbits[Nn * MW];
__device__ __nv_bfloat16 g_Xs[(size_t)BN * KS];          // X: [hi|lo|hi] (78 MB)
__device__ __nv_bfloat16 g_Wt[(size_t)HF * KS];          // W^T: [hi|hi|lo] (3 MB)

// ---------------------------------------------------------------------------
// mma.sync / ldmatrix / cp.async helpers (sm_80+, valid on plain sm_100)
// ---------------------------------------------------------------------------
__device__ __forceinline__ void ldsm4(uint32_t& r0, uint32_t& r1, uint32_t& r2,
                                      uint32_t& r3, const void* p) {
    uint32_t a = (uint32_t)__cvta_generic_to_shared(p);
    asm volatile("ldmatrix.sync.aligned.m8n8.x4.shared.b16 {%0,%1,%2,%3}, [%4];"
                 : "=r"(r0), "=r"(r1), "=r"(r2), "=r"(r3) : "r"(a));
}
__device__ __forceinline__ void ldsm4t(uint32_t& r0, uint32_t& r1, uint32_t& r2,
                                       uint32_t& r3, const void* p) {
    uint32_t a = (uint32_t)__cvta_generic_to_shared(p);
    asm volatile("ldmatrix.sync.aligned.m8n8.x4.trans.shared.b16 {%0,%1,%2,%3}, [%4];"
                 : "=r"(r0), "=r"(r1), "=r"(r2), "=r"(r3) : "r"(a));
}
__device__ __forceinline__ void mma_bf16(float* c, const uint32_t* a,
                                         uint32_t b0, uint32_t b1) {
    asm volatile(
        "mma.sync.aligned.m16n8k16.row.col.f32.bf16.bf16.f32 "
        "{%0,%1,%2,%3}, {%4,%5,%6,%7}, {%8,%9}, {%0,%1,%2,%3};"
        : "+f"(c[0]), "+f"(c[1]), "+f"(c[2]), "+f"(c[3])
        : "r"(a[0]), "r"(a[1]), "r"(a[2]), "r"(a[3]), "r"(b0), "r"(b1));
}
__device__ __forceinline__ void mma_f16(float* c, const uint32_t* a,
                                        uint32_t b0, uint32_t b1) {
    asm volatile(
        "mma.sync.aligned.m16n8k16.row.col.f32.f16.f16.f32 "
        "{%0,%1,%2,%3}, {%4,%5,%6,%7}, {%8,%9}, {%0,%1,%2,%3};"
        : "+f"(c[0]), "+f"(c[1]), "+f"(c[2]), "+f"(c[3])
        : "r"(a[0]), "r"(a[1]), "r"(a[2]), "r"(a[3]), "r"(b0), "r"(b1));
}
__device__ __forceinline__ void cp16(void* s, const void* g) {
    uint32_t sa = (uint32_t)__cvta_generic_to_shared(s);
    asm volatile("cp.async.cg.shared.global [%0], [%1], 16;" :: "r"(sa), "l"(g));
}
__device__ __forceinline__ void cp16z(void* s, const void* g, int sz) {
    uint32_t sa = (uint32_t)__cvta_generic_to_shared(s);
    asm volatile("cp.async.cg.shared.global [%0], [%1], 16, %2;"
                 :: "r"(sa), "l"(g), "r"(sz));
}
#define CP_COMMIT() asm volatile("cp.async.commit_group;" ::: "memory")
#define CP_WAIT2()  asm volatile("cp.async.wait_group 2;" ::: "memory")

// ---------------------------------------------------------------------------
// Kernel P0: w_neigh + adjacency bitmask
// ---------------------------------------------------------------------------
__global__ void prep_kernel(const float* __restrict__ W,
                            const float* __restrict__ a_neigh,
                            const int*   __restrict__ A) {
    int t = blockIdx.x * blockDim.x + threadIdx.x;
    int stride = gridDim.x * blockDim.x;
    for (int idx = t; idx < Hh * Fin; idx += stride) {
        int h = idx / Fin, f = idx % Fin;
        const float* wp = W + ((size_t)h * Fin + f) * Fout;
        const float* ap = a_neigh + h * Fout;
        float s = 0.f;
        for (int d = 0; d < Fout; d++) s += wp[d] * ap[d];
        g_wneigh[idx] = s;
    }
    for (int idx = t; idx < Nn * MW; idx += stride) {
        int i = idx / MW, c = idx % MW;
        unsigned m = 0u;
        for (int bb = 0; bb < 32; bb++) {
            int j = c * 32 + bb;
            if (j < Nn && A[i * Nn + j] != 0) m |= (1u << bb);
        }
        g_mbits[idx] = m;
    }
}

// ---------------------------------------------------------------------------
// Kernel P1: e_neigh[b,h,n] = X[b,n,:] . w_neigh[h,:]  (fp32 exact, feeds exp)
// ---------------------------------------------------------------------------
__global__ void __launch_bounds__(256) eneigh_kernel(const float* __restrict__ X) {
    __shared__ float ws[Hh * Fin];
    const int tid = threadIdx.x;
    for (int i = tid; i < Hh * Fin; i += 256) ws[i] = g_wneigh[i];
    __syncthreads();

    const int warp = tid >> 5, lane = tid & 31;
    const int row = blockIdx.x * 8 + warp;
    const float* xp = X + (size_t)row * Fin;
    float x[8];
    #pragma unroll
    for (int k = 0; k < 8; k++) x[k] = xp[lane + 32 * k];

    const int b = row / Nn, n = row % Nn;
    #pragma unroll
    for (int h = 0; h < Hh; h++) {
        float s = 0.f;
        #pragma unroll
        for (int k = 0; k < 8; k++) s = fmaf(x[k], ws[h * Fin + lane + 32 * k], s);
        #pragma unroll
        for (int o = 16; o > 0; o >>= 1) s += __shfl_xor_sync(0xffffffffu, s, o);
        if (lane == 0) g_eneigh[(size_t)(b * Hh + h) * Nn + n] = s;
    }
}

// ---------------------------------------------------------------------------
// Kernel S0: split X. Layout: [0:256)=hi, [256:512)=lo, [512:768)=hi copy.
// ---------------------------------------------------------------------------
__global__ void __launch_bounds__(256) split_x_kernel(const float* __restrict__ X) {
    const int idx = blockIdx.x * 256 + threadIdx.x;   // < BN*64
    const float4 x = ((const float4*)X)[idx];
    const int m = idx >> 6, f4 = idx & 63;
    float v[4] = {x.x, x.y, x.z, x.w};
    __nv_bfloat162 hp[2], lp[2];
    #pragma unroll
    for (int i = 0; i < 2; i++) {
        __nv_bfloat16 h0 = __float2bfloat16(v[2*i]);
        __nv_bfloat16 h1 = __float2bfloat16(v[2*i+1]);
        __nv_bfloat16 l0 = __float2bfloat16(v[2*i]   - __bfloat162float(h0));
        __nv_bfloat16 l1 = __float2bfloat16(v[2*i+1] - __bfloat162float(h1));
        hp[i].x = h0; hp[i].y = h1;
        lp[i].x = l0; lp[i].y = l1;
    }
    __nv_bfloat162* d0 = (__nv_bfloat162*)&g_Xs[(size_t)m * KS + f4 * 4];
    __nv_bfloat162* d1 = (__nv_bfloat162*)&g_Xs[(size_t)m * KS + 256 + f4 * 4];
    __nv_bfloat162* d2 = (__nv_bfloat162*)&g_Xs[(size_t)m * KS + 512 + f4 * 4];
    d0[0] = hp[0]; d0[1] = hp[1];
    d1[0] = lp[0]; d1[1] = lp[1];
    d2[0] = hp[0]; d2[1] = hp[1];
}

// ---------------------------------------------------------------------------
// Kernel S1: W^T split. Layout: [0:256)=hi, [256:512)=hi copy, [512:768)=lo.
// ---------------------------------------------------------------------------
__global__ void __launch_bounds__(256) split_w_kernel(const float* __restrict__ W) {
    const int idx = blockIdx.x * 256 + threadIdx.x;   // < HF*64
    const int col = idx >> 6, f4 = idx & 63;
    const int h = col >> 8, d = col & 255;
    #pragma unroll
    for (int i = 0; i < 4; i++) {
        int f = f4 * 4 + i;
        float v = W[((size_t)h * Fin + f) * Fout + d];
        __nv_bfloat16 hb = __float2bfloat16(v);
        __nv_bfloat16 lb = __float2bfloat16(v - __bfloat162float(hb));
        g_Wt[(size_t)col * KS + f]       = hb;
        g_Wt[(size_t)col * KS + 256 + f] = hb;
        g_Wt[(size_t)col * KS + 512 + f] = lb;
    }
}

// ---------------------------------------------------------------------------
// Kernel G1 (mma.sync + cp.async 4-stage): feats = X @ W' via 3-term split;
// epilogue writes fp16 hi/lo pair tensors for the attention stage.
// ---------------------------------------------------------------------------
__global__ void __launch_bounds__(256, 2) gemm1_mma() {
    extern __shared__ char gsm[];
    __nv_bfloat16* As = (__nv_bfloat16*)gsm;                       // [GSTG*128][LDS]
    __nv_bfloat16* Bs = (__nv_bfloat16*)(gsm + (size_t)GSTG * 128 * LDS * 2);

    const int tid  = threadIdx.x;
    const int lane = tid & 31, warp = tid >> 5;
    const int wm = warp >> 2, wn = warp & 3;          // warp grid 2x4
    const int m0 = blockIdx.x * 128, n0 = blockIdx.y * 128;

    const __nv_bfloat16* Ag = g_Xs + (size_t)m0 * KS;
    const __nv_bfloat16* Bg = g_Wt + (size_t)n0 * KS;

    // loader: 512 16B-vectors per tile per matrix; 2 per thread
    const int lrow0 = tid >> 2, lc16 = tid & 3;       // v = tid: row, col16
    const int lrow1 = (tid + 256) >> 2;               // v = tid+256 (same col16)

    #define G1_ISSUE(c) do {                                                     \
        const int _st = (c) & 3, _ko = (c) * KCH;                                \
        cp16(As + (size_t)(_st * 128 + lrow0) * LDS + lc16 * 8,                  \
             Ag + (size_t)lrow0 * KS + _ko + lc16 * 8);                          \
        cp16(As + (size_t)(_st * 128 + lrow1) * LDS + lc16 * 8,                  \
             Ag + (size_t)lrow1 * KS + _ko + lc16 * 8);                          \
        cp16(Bs + (size_t)(_st * 128 + lrow0) * LDS + lc16 * 8,                  \
             Bg + (size_t)lrow0 * KS + _ko + lc16 * 8);                          \
        cp16(Bs + (size_t)(_st * 128 + lrow1) * LDS + lc16 * 8,                  \
             Bg + (size_t)lrow1 * KS + _ko + lc16 * 8);                          \
    } while (0)

    G1_ISSUE(0); CP_COMMIT();
    G1_ISSUE(1); CP_COMMIT();
    G1_ISSUE(2); CP_COMMIT();

    float acc[4][4][4];
    #pragma unroll
    for (int i = 0; i < 4; i++)
        #pragma unroll
        for (int j = 0; j < 4; j++)
            #pragma unroll
            for (int q = 0; q < 4; q++) acc[i][j][q] = 0.f;

    for (int c = 0; c < NKC; c++) {
        CP_WAIT2();               // stage c landed (in this thread)
        __syncthreads();          // visible to all; all warps done with mma(c-1)
        if (c + 3 < NKC) G1_ISSUE(c + 3);
        CP_COMMIT();              // uniform group count (empty at tail)

        const int sb = (c & 3) * 128;
        #pragma unroll
        for (int ks = 0; ks < 2; ks++) {
            uint32_t ra[4][4], rb[2][4];
            #pragma unroll
            for (int am = 0; am < 4; am++)
                ldsm4(ra[am][0], ra[am][1], ra[am][2], ra[am][3],
                      As + (size_t)(sb + wm * 64 + am * 16 + (lane & 15)) * LDS
                         + ks * 16 + (lane >> 4) * 8);
            #pragma unroll
            for (int bn = 0; bn < 2; bn++)
                ldsm4(rb[bn][0], rb[bn][1], rb[bn][2], rb[bn][3],
                      Bs + (size_t)(sb + wn * 32 + bn * 16 + (lane & 7)
                                    + ((lane >> 4) << 3)) * LDS
                         + ks * 16 + ((lane >> 3) & 1) * 8);
            #pragma unroll
            for (int am = 0; am < 4; am++)
                #pragma unroll
                for (int an = 0; an < 4; an++)
                    mma_bf16(acc[am][an], ra[am],
                             rb[an >> 1][(an & 1) * 2], rb[an >> 1][(an & 1) * 2 + 1]);
        }
    }

    // epilogue: split fp32 result into fp16 hi + lo pair tensors
    #pragma unroll
    for (int am = 0; am < 4; am++) {
        const int row = m0 + wm * 64 + am * 16 + (lane >> 2);
        #pragma unroll
        for (int an = 0; an < 4; an++) {
            const int col = n0 + wn * 32 + an * 8 + (lane & 3) * 2;
            #pragma unroll
            for (int rr = 0; rr < 2; rr++) {
                const size_t off = (size_t)(row + rr * 8) * HF + col;
                float f0 = acc[am][an][rr * 2], f1 = acc[am][an][rr * 2 + 1];
                __half h0 = __float2half_rn(f0);
                __half h1 = __float2half_rn(f1);
                __half2 hp, lp;
                hp.x = h0; hp.y = h1;
                lp.x = __float2half_rn(f0 - __half2float(h0));
                lp.y = __float2half_rn(f1 - __half2float(h1));
                *(__half2*)(g_fhi + off) = hp;
                *(__half2*)(g_flo + off) = lp;
            }
        }
    }
}

// ---------------------------------------------------------------------------
// Kernel A2 (mma.sync + cp.async): masked softmax + P@V.
// P = fp16(u_j) exactly; S_i summed from the SAME fp16 values -> exactly
// normalized weights. V = fp16 hi/lo, 2 segments: P·Vhi + P·Vlo. K = 2*208.
// ---------------------------------------------------------------------------
__global__ void __launch_bounds__(256) attn_mma(const float* __restrict__ bias,
                                                float* __restrict__ out) {
    extern __shared__ char sm[];
    __half*   Ph   = (__half*)(sm + OF_PH);     // [128][LDPH]
    __half*   Vs   = (__half*)(sm + OF_VS);     // [VSTG][16][LDV]
    __half*   uh   = (__half*)(sm + OF_UH);     // [NJP]
    float*    Sinv = (float*)(sm + OF_SI);      // [128]
    float*    red  = (float*)(sm + OF_RED);     // [32]
    unsigned* mb   = (unsigned*)(sm + OF_MB);   // [Nn*MW]

    const int tid = threadIdx.x, lane = tid & 31, warp = tid >> 5;
    const int bh = blockIdx.x, b = bh >> 3, h = bh & 7;
    const int i0 = blockIdx.y * 128;
    const int wm = warp >> 2, wn = warp & 3;    // warp grid 2x4 (64i x 64d)

    const __half* fbh = g_fhi + (size_t)b * Nn * HF + h * Fout;
    const __half* fbl = g_flo + (size_t)b * Nn * HF + h * Fout;

    // V stage loader: stage = step&3; seg 0 -> hi, seg 1 -> lo
    const int vrow0 = tid >> 5, vc16a = tid & 31;     // v = tid
    #define AT_ISSUE(stp) do {                                                   \
        const int _st = (stp) & 3, _seg = (stp) / 13;                            \
        const int _jt = (stp) - _seg * 13;                                       \
        const __half* _src = _seg ? fbl : fbh;                                   \
        _Pragma("unroll")                                                        \
        for (int _q = 0; _q < 2; _q++) {                                         \
            int _v = tid + _q * 256, _row = _v >> 5, _c16 = _v & 31;             \
            int _j = _jt * 16 + _row;                                            \
            int _sz = (_j < Nn) ? 16 : 0;                                        \
            const __half* _g = _src + (size_t)(_j < Nn ? _j : 0) * HF + _c16 * 8;\
            cp16z(Vs + (size_t)(_st * 16 + _row) * LDV + _c16 * 8, _g, _sz);     \
        }                                                                        \
    } while (0)

    // prologue V loads overlap softmax/P-build below
    AT_ISSUE(0); CP_COMMIT();
    AT_ISSUE(1); CP_COMMIT();
    AT_ISSUE(2); CP_COMMIT();

    for (int i = tid; i < Nn * MW; i += 256) mb[i] = g_mbits[i];

    // softmax weights: u_j = exp(e_j - gmax), quantized to fp16
    const float* ep = g_eneigh + (size_t)bh * Nn;
    float e = (tid < Nn) ? ep[tid] : -1e30f;
    float m = e;
    #pragma unroll
    for (int o = 16; o > 0; o >>= 1) m = fmaxf(m, __shfl_xor_sync(0xffffffffu, m, o));
    if (lane == 0) red[warp] = m;
    __syncthreads();
    if (tid == 0) {
        float mm = red[0];
        for (int w = 1; w < 8; w++) mm = fmaxf(mm, red[w]);
        red[0] = mm;
    }
    __syncthreads();
    const float gmax = red[0];
    if (tid < NJP)
        uh[tid] = (tid < Nn) ? __float2half_rn(__expf(e - gmax)) : __half(0.f);
    __syncthreads();

    // build P tile (fp16, masked) + row sums from the SAME quantized values
    for (int t = tid; t < 128 * NPR; t += 256) {
        const int i = t / NPR, jp = t - i * NPR;
        const int ig = i0 + i;
        uint32_t mw_ = 0u;
        if (ig < Nn) {
            const unsigned* mrow = mb + ig * MW;
            const int j0 = jp * 2, j1 = j0 + 1;
            if ((mrow[j0 >> 5] >> (j0 & 31)) & 1u) mw_ |= 0x0000FFFFu;
            if ((mrow[j1 >> 5] >> (j1 & 31)) & 1u) mw_ |= 0xFFFF0000u;
        }
        const uint32_t uhp = ((const uint32_t*)uh)[jp];
        ((uint32_t*)(Ph + (size_t)i * LDPH))[jp] = uhp & mw_;
    }
    for (int il = warp; il < 128; il += 8) {
        const int ig = i0 + il;
        float s = 0.f;
        if (ig < Nn) {
            const unsigned* mrow = mb + ig * MW;
            for (int j = lane; j < Nn; j += 32)
                if (mrow[j >> 5] & (1u << (j & 31))) s += __half2float(uh[j]);
        }
        #pragma unroll
        for (int o = 16; o > 0; o >>= 1) s += __shfl_xor_sync(0xffffffffu, s, o);
        if (lane == 0) Sinv[il] = (ig < Nn) ? (1.f / s) : 0.f;
    }
    __syncthreads();

    // K-loop: 26 steps of k=16 (2 segments x 13), 4-stage cp.async
    float acc[4][8][4];
    #pragma unroll
    for (int i = 0; i < 4; i++)
        #pragma unroll
        for (int j = 0; j < 8; j++)
            #pragma unroll
            for (int q = 0; q < 4; q++) acc[i][j][q] = 0.f;

    for (int step = 0; step < NSTEP; step++) {
        CP_WAIT2();
        __syncthreads();
        if (step + 3 < NSTEP) AT_ISSUE(step + 3);
        CP_COMMIT();

        const int seg = step / 13;
        const int kc = (step - seg * 13) * 16;
        const int vb = (step & 3) * 16;

        uint32_t ra[4][4], rb[4][4];
        #pragma unroll
        for (int am = 0; am < 4; am++)
            ldsm4(ra[am][0], ra[am][1], ra[am][2], ra[am][3],
                  Ph + (size_t)(wm * 64 + am * 16 + (lane & 15)) * LDPH
                     + kc + (lane >> 4) * 8);
        #pragma unroll
        for (int q = 0; q < 4; q++)
            ldsm4t(rb[q][0], rb[q][1], rb[q][2], rb[q][3],
                   Vs + (size_t)(vb + (lane & 15)) * LDV
                      + wn * 64 + q * 16 + ((lane >> 4) << 3));
        #pragma unroll
        for (int am = 0; am < 4; am++)
            #pragma unroll
            for (int an = 0; an < 8; an++)
                mma_f16(acc[am][an], ra[am],
                        rb[an >> 1][(an & 1) * 2], rb[an >> 1][(an & 1) * 2 + 1]);
    }

    // epilogue: scale by Sinv, add bias, store fp32
    #pragma unroll
    for (int am = 0; am < 4; am++) {
        const int il = wm * 64 + am * 16 + (lane >> 2);
        const int ig0 = i0 + il, ig1 = ig0 + 8;
        const float si0 = Sinv[il], si1 = Sinv[il + 8];
        #pragma unroll
        for (int an = 0; an < 8; an++) {
            const int d = wn * 64 + an * 8 + (lane & 3) * 2;
            const float bv0 = bias[h * Fout + d];
            const float bv1 = bias[h * Fout + d + 1];
            if (ig0 < Nn) {
                float* p = out + (size_t)(b * Nn + ig0) * HF + h * Fout + d;
                *(float2*)p = make_float2(fmaf(acc[am][an][0], si0, bv0),
                                          fmaf(acc[am][an][1], si0, bv1));
            }
            if (ig1 < Nn) {
                float* p = out + (size_t)(b * Nn + ig1) * HF + h * Fout + d;
                *(float2*)p = make_float2(fmaf(acc[am][an][2], si1, bv0),
                                          fmaf(acc[am][an][3], si1, bv1));
            }
        }
    }
}

// ---------------------------------------------------------------------------
extern "C" void kernel_launch(void* const* d_in, const int* in_sizes, int n_in,
                              void* d_out, int out_size) {
    const float* X       = (const float*)d_in[0];
    const int*   A       = (const int*)  d_in[1];
    const float* W       = (const float*)d_in[2];
    // d_in[3] = a_self: no effect on output (softmax row-constant cancels)
    const float* a_neigh = (const float*)d_in[4];
    const float* bias    = (const float*)d_in[5];
    float* out = (float*)d_out;

    prep_kernel<<<16, 256>>>(W, a_neigh, A);
    eneigh_kernel<<<BN / 8, 256>>>(X);
    split_x_kernel<<<BN * 64 / 256, 256>>>(X);
    split_w_kernel<<<HF * 64 / 256, 256>>>(W);

    cudaFuncSetAttribute(gemm1_mma, cudaFuncAttributeMaxDynamicSharedMemorySize,
                         G1_SMEM);
    gemm1_mma<<<dim3(BN / 128, HF / 128), 256, G1_SMEM>>>();

    cudaFuncSetAttribute(attn_mma, cudaFuncAttributeMaxDynamicSharedMemorySize,
                         ATTN_SMEM);
    attn_mma<<<dim3(Bn * Hh, 2), 256, ATTN_SMEM>>>(bias, out);
}

// round 8
// speedup vs baseline: 2.1718x; 1.1106x over previous
#include <cuda_runtime.h>
#include <cuda_fp16.h>
#include <math.h>
#include <stdint.h>

// Problem constants
#define Bn   256
#define Nn   199
#define Fin  256
#define Hh   8
#define Fout 256
#define HF   2048          // Hh * Fout
#define BN   (Bn * Nn)     // 50944
#define MW   7             // mask words per row

// gemm1 (mma.sync) tiling — 2-segment fp16 split: [Xhi|Xlo] x [Whi|Whi]
#define KS   512           // 2 * 256
#define KCH  32            // K chunk per smem stage
#define NKC  (KS / KCH)    // 16
#define LDS  40            // gemm1 smem row stride (halfs): 80B, conflict-free
#define GSTG 4             // cp.async stages
#define G1_SMEM (2 * GSTG * 128 * LDS * 2)   // 81920 B

// attn (mma.sync) tiling — P fp16 exact, V fp16 hi/lo: 2 segments
#define NJP   208          // padded j (13*16)
#define NPR   104          // j pairs
#define LDPH  216          // P smem row stride (halfs): 432B -> conflict-free
#define LDV   264          // V smem row stride (halfs): 528B -> conflict-free
#define NSTEP 26           // 2 segments * 13 k16-steps
#define VSTG  4

// attn smem byte offsets (all 16B aligned)
#define OF_PH 0
#define OF_VS 55296        // 128*216*2
#define OF_UH 89088        // + 4*16*264*2
#define OF_SI 89504        // + 208*2
#define OF_RED 90016
#define OF_MB 90144
#define ATTN_SMEM 95744    // 90144 + 199*7*4 = 95716, rounded

// ---------------------------------------------------------------------------
// Scratch (device globals — no runtime allocation allowed)
// ---------------------------------------------------------------------------
__device__ __half        g_fhi[(size_t)BN * HF];         // feats hi (209 MB)
__device__ __half        g_flo[(size_t)BN * HF];         // feats lo (209 MB)
__device__ float         g_eneigh[(size_t)Bn * Hh * Nn];
__device__ float         g_wneigh[Hh * Fin];
__device__ unsigned      g_mbits[Nn * MW];
__device__ __half        g_Xs[(size_t)BN * KS];          // X: [hi|lo] (52 MB)
__device__ __half        g_Wt[(size_t)HF * KS];          // W^T: [hi|hi] (2 MB)

// ---------------------------------------------------------------------------
// mma.sync / ldmatrix / cp.async helpers (sm_80+, valid on plain sm_100)
// ---------------------------------------------------------------------------
__device__ __forceinline__ void ldsm4(uint32_t& r0, uint32_t& r1, uint32_t& r2,
                                      uint32_t& r3, const void* p) {
    uint32_t a = (uint32_t)__cvta_generic_to_shared(p);
    asm volatile("ldmatrix.sync.aligned.m8n8.x4.shared.b16 {%0,%1,%2,%3}, [%4];"
                 : "=r"(r0), "=r"(r1), "=r"(r2), "=r"(r3) : "r"(a));
}
__device__ __forceinline__ void ldsm4t(uint32_t& r0, uint32_t& r1, uint32_t& r2,
                                       uint32_t& r3, const void* p) {
    uint32_t a = (uint32_t)__cvta_generic_to_shared(p);
    asm volatile("ldmatrix.sync.aligned.m8n8.x4.trans.shared.b16 {%0,%1,%2,%3}, [%4];"
                 : "=r"(r0), "=r"(r1), "=r"(r2), "=r"(r3) : "r"(a));
}
__device__ __forceinline__ void mma_f16(float* c, const uint32_t* a,
                                        uint32_t b0, uint32_t b1) {
    asm volatile(
        "mma.sync.aligned.m16n8k16.row.col.f32.f16.f16.f32 "
        "{%0,%1,%2,%3}, {%4,%5,%6,%7}, {%8,%9}, {%0,%1,%2,%3};"
        : "+f"(c[0]), "+f"(c[1]), "+f"(c[2]), "+f"(c[3])
        : "r"(a[0]), "r"(a[1]), "r"(a[2]), "r"(a[3]), "r"(b0), "r"(b1));
}
__device__ __forceinline__ void cp16(void* s, const void* g) {
    uint32_t sa = (uint32_t)__cvta_generic_to_shared(s);
    asm volatile("cp.async.cg.shared.global [%0], [%1], 16;" :: "r"(sa), "l"(g));
}
__device__ __forceinline__ void cp16z(void* s, const void* g, int sz) {
    uint32_t sa = (uint32_t)__cvta_generic_to_shared(s);
    asm volatile("cp.async.cg.shared.global [%0], [%1], 16, %2;"
                 :: "r"(sa), "l"(g), "r"(sz));
}
#define CP_COMMIT() asm volatile("cp.async.commit_group;" ::: "memory")
#define CP_WAIT2()  asm volatile("cp.async.wait_group 2;" ::: "memory")

// ---------------------------------------------------------------------------
// Kernel P0: w_neigh + adjacency bitmask
// ---------------------------------------------------------------------------
__global__ void prep_kernel(const float* __restrict__ W,
                            const float* __restrict__ a_neigh,
                            const int*   __restrict__ A) {
    int t = blockIdx.x * blockDim.x + threadIdx.x;
    int stride = gridDim.x * blockDim.x;
    for (int idx = t; idx < Hh * Fin; idx += stride) {
        int h = idx / Fin, f = idx % Fin;
        const float* wp = W + ((size_t)h * Fin + f) * Fout;
        const float* ap = a_neigh + h * Fout;
        float s = 0.f;
        for (int d = 0; d < Fout; d++) s += wp[d] * ap[d];
        g_wneigh[idx] = s;
    }
    for (int idx = t; idx < Nn * MW; idx += stride) {
        int i = idx / MW, c = idx % MW;
        unsigned m = 0u;
        for (int bb = 0; bb < 32; bb++) {
            int j = c * 32 + bb;
            if (j < Nn && A[i * Nn + j] != 0) m |= (1u << bb);
        }
        g_mbits[idx] = m;
    }
}

// ---------------------------------------------------------------------------
// Kernel P1: e_neigh[b,h,n] = X[b,n,:] . w_neigh[h,:]  (fp32 exact, feeds exp)
// ---------------------------------------------------------------------------
__global__ void __launch_bounds__(256) eneigh_kernel(const float* __restrict__ X) {
    __shared__ float ws[Hh * Fin];
    const int tid = threadIdx.x;
    for (int i = tid; i < Hh * Fin; i += 256) ws[i] = g_wneigh[i];
    __syncthreads();

    const int warp = tid >> 5, lane = tid & 31;
    const int row = blockIdx.x * 8 + warp;
    const float* xp = X + (size_t)row * Fin;
    float x[8];
    #pragma unroll
    for (int k = 0; k < 8; k++) x[k] = xp[lane + 32 * k];

    const int b = row / Nn, n = row % Nn;
    #pragma unroll
    for (int h = 0; h < Hh; h++) {
        float s = 0.f;
        #pragma unroll
        for (int k = 0; k < 8; k++) s = fmaf(x[k], ws[h * Fin + lane + 32 * k], s);
        #pragma unroll
        for (int o = 16; o > 0; o >>= 1) s += __shfl_xor_sync(0xffffffffu, s, o);
        if (lane == 0) g_eneigh[(size_t)(b * Hh + h) * Nn + n] = s;
    }
}

// ---------------------------------------------------------------------------
// Kernel S0: split X into fp16 hi|lo along K. One thread per 4 floats.
// ---------------------------------------------------------------------------
__global__ void __launch_bounds__(256) split_x_kernel(const float* __restrict__ X) {
    const int idx = blockIdx.x * 256 + threadIdx.x;   // < BN*64
    const float4 x = ((const float4*)X)[idx];
    const int m = idx >> 6, f4 = idx & 63;
    float v[4] = {x.x, x.y, x.z, x.w};
    __half2 hp[2], lp[2];
    #pragma unroll
    for (int i = 0; i < 2; i++) {
        __half h0 = __float2half_rn(v[2*i]);
        __half h1 = __float2half_rn(v[2*i+1]);
        hp[i].x = h0; hp[i].y = h1;
        lp[i].x = __float2half_rn(v[2*i]   - __half2float(h0));
        lp[i].y = __float2half_rn(v[2*i+1] - __half2float(h1));
    }
    __half2* d0 = (__half2*)&g_Xs[(size_t)m * KS + f4 * 4];
    __half2* d1 = (__half2*)&g_Xs[(size_t)m * KS + 256 + f4 * 4];
    d0[0] = hp[0]; d0[1] = hp[1];
    d1[0] = lp[0]; d1[1] = lp[1];
}

// ---------------------------------------------------------------------------
// Kernel S1: W^T fp16: g_Wt[col][f] = hi(W[h][f][d]) in both segments.
// ---------------------------------------------------------------------------
__global__ void __launch_bounds__(256) split_w_kernel(const float* __restrict__ W) {
    const int idx = blockIdx.x * 256 + threadIdx.x;   // < HF*64
    const int col = idx >> 6, f4 = idx & 63;
    const int h = col >> 8, d = col & 255;
    #pragma unroll
    for (int i = 0; i < 4; i++) {
        int f = f4 * 4 + i;
        float v = W[((size_t)h * Fin + f) * Fout + d];
        __half hb = __float2half_rn(v);
        g_Wt[(size_t)col * KS + f]       = hb;
        g_Wt[(size_t)col * KS + 256 + f] = hb;
    }
}

// ---------------------------------------------------------------------------
// Kernel G1 (mma.sync + cp.async 4-stage): feats = X @ W' via 2-seg fp16 split;
// epilogue writes fp16 hi/lo pair tensors for the attention stage.
// Grid: (16 n-tiles, 398 m-tiles) — consecutive CTAs share the A tile in L2.
// ---------------------------------------------------------------------------
__global__ void __launch_bounds__(256, 2) gemm1_mma() {
    extern __shared__ char gsm[];
    __half* As = (__half*)gsm;                              // [GSTG*128][LDS]
    __half* Bs = (__half*)(gsm + (size_t)GSTG * 128 * LDS * 2);

    const int tid  = threadIdx.x;
    const int lane = tid & 31, warp = tid >> 5;
    const int wm = warp >> 2, wn = warp & 3;          // warp grid 2x4
    const int m0 = blockIdx.y * 128, n0 = blockIdx.x * 128;

    const __half* Ag = g_Xs + (size_t)m0 * KS;
    const __half* Bg = g_Wt + (size_t)n0 * KS;

    // loader: 512 16B-vectors per tile per matrix; 2 per thread
    const int lrow0 = tid >> 2, lc16 = tid & 3;
    const int lrow1 = (tid + 256) >> 2;

    #define G1_ISSUE(c) do {                                                     \
        const int _st = (c) & 3, _ko = (c) * KCH;                                \
        cp16(As + (size_t)(_st * 128 + lrow0) * LDS + lc16 * 8,                  \
             Ag + (size_t)lrow0 * KS + _ko + lc16 * 8);                          \
        cp16(As + (size_t)(_st * 128 + lrow1) * LDS + lc16 * 8,                  \
             Ag + (size_t)lrow1 * KS + _ko + lc16 * 8);                          \
        cp16(Bs + (size_t)(_st * 128 + lrow0) * LDS + lc16 * 8,                  \
             Bg + (size_t)lrow0 * KS + _ko + lc16 * 8);                          \
        cp16(Bs + (size_t)(_st * 128 + lrow1) * LDS + lc16 * 8,                  \
             Bg + (size_t)lrow1 * KS + _ko + lc16 * 8);                          \
    } while (0)

    G1_ISSUE(0); CP_COMMIT();
    G1_ISSUE(1); CP_COMMIT();
    G1_ISSUE(2); CP_COMMIT();

    float acc[4][4][4];
    #pragma unroll
    for (int i = 0; i < 4; i++)
        #pragma unroll
        for (int j = 0; j < 4; j++)
            #pragma unroll
            for (int q = 0; q < 4; q++) acc[i][j][q] = 0.f;

    for (int c = 0; c < NKC; c++) {
        CP_WAIT2();               // stage c landed (in this thread)
        __syncthreads();          // visible to all; all warps done with mma(c-1)
        if (c + 3 < NKC) G1_ISSUE(c + 3);
        CP_COMMIT();              // uniform group count (empty at tail)

        const int sb = (c & 3) * 128;
        #pragma unroll
        for (int ks = 0; ks < 2; ks++) {
            uint32_t ra[4][4], rb[2][4];
            #pragma unroll
            for (int am = 0; am < 4; am++)
                ldsm4(ra[am][0], ra[am][1], ra[am][2], ra[am][3],
                      As + (size_t)(sb + wm * 64 + am * 16 + (lane & 15)) * LDS
                         + ks * 16 + (lane >> 4) * 8);
            #pragma unroll
            for (int bn = 0; bn < 2; bn++)
                ldsm4(rb[bn][0], rb[bn][1], rb[bn][2], rb[bn][3],
                      Bs + (size_t)(sb + wn * 32 + bn * 16 + (lane & 7)
                                    + ((lane >> 4) << 3)) * LDS
                         + ks * 16 + ((lane >> 3) & 1) * 8);
            #pragma unroll
            for (int am = 0; am < 4; am++)
                #pragma unroll
                for (int an = 0; an < 4; an++)
                    mma_f16(acc[am][an], ra[am],
                            rb[an >> 1][(an & 1) * 2], rb[an >> 1][(an & 1) * 2 + 1]);
        }
    }

    // epilogue: split fp32 result into fp16 hi + lo pair tensors
    #pragma unroll
    for (int am = 0; am < 4; am++) {
        const int row = m0 + wm * 64 + am * 16 + (lane >> 2);
        #pragma unroll
        for (int an = 0; an < 4; an++) {
            const int col = n0 + wn * 32 + an * 8 + (lane & 3) * 2;
            #pragma unroll
            for (int rr = 0; rr < 2; rr++) {
                const size_t off = (size_t)(row + rr * 8) * HF + col;
                float f0 = acc[am][an][rr * 2], f1 = acc[am][an][rr * 2 + 1];
                __half h0 = __float2half_rn(f0);
                __half h1 = __float2half_rn(f1);
                __half2 hp, lp;
                hp.x = h0; hp.y = h1;
                lp.x = __float2half_rn(f0 - __half2float(h0));
                lp.y = __float2half_rn(f1 - __half2float(h1));
                *(__half2*)(g_fhi + off) = hp;
                *(__half2*)(g_flo + off) = lp;
            }
        }
    }
}

// ---------------------------------------------------------------------------
// Kernel A2 (mma.sync + cp.async): masked softmax + P@V.
// P = fp16(u_j) exactly; S_i summed from the SAME fp16 values -> exactly
// normalized weights. V = fp16 hi/lo, 2 segments: P·Vhi + P·Vlo. K = 2*208.
// Grid: (2 i-tiles, 4096 bh) — the pair sharing a V slice runs adjacently.
// ---------------------------------------------------------------------------
__global__ void __launch_bounds__(256) attn_mma(const float* __restrict__ bias,
                                                float* __restrict__ out) {
    extern __shared__ char sm[];
    __half*   Ph   = (__half*)(sm + OF_PH);     // [128][LDPH]
    __half*   Vs   = (__half*)(sm + OF_VS);     // [VSTG][16][LDV]
    __half*   uh   = (__half*)(sm + OF_UH);     // [NJP]
    float*    Sinv = (float*)(sm + OF_SI);      // [128]
    float*    red  = (float*)(sm + OF_RED);     // [32]
    unsigned* mb   = (unsigned*)(sm + OF_MB);   // [Nn*MW]

    const int tid = threadIdx.x, lane = tid & 31, warp = tid >> 5;
    const int bh = blockIdx.y, b = bh >> 3, h = bh & 7;
    const int i0 = blockIdx.x * 128;
    const int wm = warp >> 2, wn = warp & 3;    // warp grid 2x4 (64i x 64d)

    const __half* fbh = g_fhi + (size_t)b * Nn * HF + h * Fout;
    const __half* fbl = g_flo + (size_t)b * Nn * HF + h * Fout;

    // V stage loader: stage = step&3; seg 0 -> hi, seg 1 -> lo
    #define AT_ISSUE(stp) do {                                                   \
        const int _st = (stp) & 3, _seg = (stp) / 13;                            \
        const int _jt = (stp) - _seg * 13;                                       \
        const __half* _src = _seg ? fbl : fbh;                                   \
        _Pragma("unroll")                                                        \
        for (int _q = 0; _q < 2; _q++) {                                         \
            int _v = tid + _q * 256, _row = _v >> 5, _c16 = _v & 31;             \
            int _j = _jt * 16 + _row;                                            \
            int _sz = (_j < Nn) ? 16 : 0;                                        \
            const __half* _g = _src + (size_t)(_j < Nn ? _j : 0) * HF + _c16 * 8;\
            cp16z(Vs + (size_t)(_st * 16 + _row) * LDV + _c16 * 8, _g, _sz);     \
        }                                                                        \
    } while (0)

    // prologue V loads overlap softmax/P-build below
    AT_ISSUE(0); CP_COMMIT();
    AT_ISSUE(1); CP_COMMIT();
    AT_ISSUE(2); CP_COMMIT();

    for (int i = tid; i < Nn * MW; i += 256) mb[i] = g_mbits[i];

    // softmax weights: u_j = exp(e_j - gmax), quantized to fp16
    const float* ep = g_eneigh + (size_t)bh * Nn;
    float e = (tid < Nn) ? ep[tid] : -1e30f;
    float m = e;
    #pragma unroll
    for (int o = 16; o > 0; o >>= 1) m = fmaxf(m, __shfl_xor_sync(0xffffffffu, m, o));
    if (lane == 0) red[warp] = m;
    __syncthreads();
    if (tid == 0) {
        float mm = red[0];
        for (int w = 1; w < 8; w++) mm = fmaxf(mm, red[w]);
        red[0] = mm;
    }
    __syncthreads();
    const float gmax = red[0];
    if (tid < NJP)
        uh[tid] = (tid < Nn) ? __float2half_rn(__expf(e - gmax)) : __half(0.f);
    __syncthreads();

    // build P tile (fp16, masked) + row sums from the SAME quantized values
    for (int t = tid; t < 128 * NPR; t += 256) {
        const int i = t / NPR, jp = t - i * NPR;
        const int ig = i0 + i;
        uint32_t mw_ = 0u;
        if (ig < Nn) {
            const unsigned* mrow = mb + ig * MW;
            const int j0 = jp * 2, j1 = j0 + 1;
            if ((mrow[j0 >> 5] >> (j0 & 31)) & 1u) mw_ |= 0x0000FFFFu;
            if ((mrow[j1 >> 5] >> (j1 & 31)) & 1u) mw_ |= 0xFFFF0000u;
        }
        const uint32_t uhp = ((const uint32_t*)uh)[jp];
        ((uint32_t*)(Ph + (size_t)i * LDPH))[jp] = uhp & mw_;
    }
    for (int il = warp; il < 128; il += 8) {
        const int ig = i0 + il;
        float s = 0.f;
        if (ig < Nn) {
            const unsigned* mrow = mb + ig * MW;
            for (int j = lane; j < Nn; j += 32)
                if (mrow[j >> 5] & (1u << (j & 31))) s += __half2float(uh[j]);
        }
        #pragma unroll
        for (int o = 16; o > 0; o >>= 1) s += __shfl_xor_sync(0xffffffffu, s, o);
        if (lane == 0) Sinv[il] = (ig < Nn) ? (1.f / s) : 0.f;
    }
    __syncthreads();

    // K-loop: 26 steps of k=16 (2 segments x 13), 4-stage cp.async
    float acc[4][8][4];
    #pragma unroll
    for (int i = 0; i < 4; i++)
        #pragma unroll
        for (int j = 0; j < 8; j++)
            #pragma unroll
            for (int q = 0; q < 4; q++) acc[i][j][q] = 0.f;

    for (int step = 0; step < NSTEP; step++) {
        CP_WAIT2();
        __syncthreads();
        if (step + 3 < NSTEP) AT_ISSUE(step + 3);
        CP_COMMIT();

        const int seg = step / 13;
        const int kc = (step - seg * 13) * 16;
        const int vb = (step & 3) * 16;

        uint32_t ra[4][4], rb[4][4];
        #pragma unroll
        for (int am = 0; am < 4; am++)
            ldsm4(ra[am][0], ra[am][1], ra[am][2], ra[am][3],
                  Ph + (size_t)(wm * 64 + am * 16 + (lane & 15)) * LDPH
                     + kc + (lane >> 4) * 8);
        #pragma unroll
        for (int q = 0; q < 4; q++)
            ldsm4t(rb[q][0], rb[q][1], rb[q][2], rb[q][3],
                   Vs + (size_t)(vb + (lane & 15)) * LDV
                      + wn * 64 + q * 16 + ((lane >> 4) << 3));
        #pragma unroll
        for (int am = 0; am < 4; am++)
            #pragma unroll
            for (int an = 0; an < 8; an++)
                mma_f16(acc[am][an], ra[am],
                        rb[an >> 1][(an & 1) * 2], rb[an >> 1][(an & 1) * 2 + 1]);
    }

    // epilogue: scale by Sinv, add bias, store fp32
    #pragma unroll
    for (int am = 0; am < 4; am++) {
        const int il = wm * 64 + am * 16 + (lane >> 2);
        const int ig0 = i0 + il, ig1 = ig0 + 8;
        const float si0 = Sinv[il], si1 = Sinv[il + 8];
        #pragma unroll
        for (int an = 0; an < 8; an++) {
            const int d = wn * 64 + an * 8 + (lane & 3) * 2;
            const float bv0 = bias[h * Fout + d];
            const float bv1 = bias[h * Fout + d + 1];
            if (ig0 < Nn) {
                float* p = out + (size_t)(b * Nn + ig0) * HF + h * Fout + d;
                *(float2*)p = make_float2(fmaf(acc[am][an][0], si0, bv0),
                                          fmaf(acc[am][an][1], si0, bv1));
            }
            if (ig1 < Nn) {
                float* p = out + (size_t)(b * Nn + ig1) * HF + h * Fout + d;
                *(float2*)p = make_float2(fmaf(acc[am][an][2], si1, bv0),
                                          fmaf(acc[am][an][3], si1, bv1));
            }
        }
    }
}

// ---------------------------------------------------------------------------
extern "C" void kernel_launch(void* const* d_in, const int* in_sizes, int n_in,
                              void* d_out, int out_size) {
    const float* X       = (const float*)d_in[0];
    const int*   A       = (const int*)  d_in[1];
    const float* W       = (const float*)d_in[2];
    // d_in[3] = a_self: no effect on output (softmax row-constant cancels)
    const float* a_neigh = (const float*)d_in[4];
    const float* bias    = (const float*)d_in[5];
    float* out = (float*)d_out;

    prep_kernel<<<64, 256>>>(W, a_neigh, A);
    eneigh_kernel<<<BN / 8, 256>>>(X);
    split_x_kernel<<<BN * 64 / 256, 256>>>(X);
    split_w_kernel<<<HF * 64 / 256, 256>>>(W);

    cudaFuncSetAttribute(gemm1_mma, cudaFuncAttributeMaxDynamicSharedMemorySize,
                         G1_SMEM);
    gemm1_mma<<<dim3(HF / 128, BN / 128), 256, G1_SMEM>>>();

    cudaFuncSetAttribute(attn_mma, cudaFuncAttributeMaxDynamicSharedMemorySize,
                         ATTN_SMEM);
    attn_mma<<<dim3(2, Bn * Hh), 256, ATTN_SMEM>>>(bias, out);
}

// round 9
// speedup vs baseline: 3.2054x; 1.4760x over previous
#include <cuda_runtime.h>
#include <cuda_fp16.h>
#include <math.h>
#include <stdint.h>

// Problem constants
#define Bn   256
#define Nn   199
#define Fin  256
#define Hh   8
#define Fout 256
#define HF   2048          // Hh * Fout
#define BN   (Bn * Nn)     // 50944
#define MW   7             // mask words per row

// gemm1 (mma.sync) tiling — single-segment fp16: fp16(X) @ fp16(W)
#define KS   256
#define KCH  32            // K chunk per smem stage
#define NKC  (KS / KCH)    // 8
#define LDS  40            // gemm1 smem row stride (halfs): 80B, conflict-free
#define GSTG 4             // cp.async stages
#define G1_SMEM (2 * GSTG * 128 * LDS * 2)   // 81920 B

// attn (mma.sync) tiling — P fp16 exact-normalized, V fp16 single segment
#define NJP   208          // padded j (13*16)
#define NPR   104          // j pairs
#define LDPH  216          // P smem row stride (halfs): 432B -> conflict-free
#define LDV   264          // V smem row stride (halfs): 528B -> conflict-free
#define NSTEP 13           // 13 k16-steps (K = 208)
#define VSTG  4

// attn smem byte offsets (all 16B aligned)
#define OF_PH 0
#define OF_VS 55296        // 128*216*2
#define OF_UH 89088        // + 4*16*264*2
#define OF_SI 89504        // + 208*2
#define OF_RED 90016
#define OF_MB 90144
#define ATTN_SMEM 95744    // 90144 + 199*7*4 = 95716, rounded

// ---------------------------------------------------------------------------
// Scratch (device globals — no runtime allocation allowed)
// ---------------------------------------------------------------------------
__device__ __half        g_fhi[(size_t)BN * HF];         // feats fp16 (209 MB)
__device__ float         g_eneigh[(size_t)Bn * Hh * Nn];
__device__ float         g_wneigh[Hh * Fin];
__device__ unsigned      g_mbits[Nn * MW];
__device__ __half        g_Xs[(size_t)BN * KS];          // fp16(X) (26 MB)
__device__ __half        g_Wt[(size_t)HF * KS];          // fp16(W^T) (1 MB)

// ---------------------------------------------------------------------------
// mma.sync / ldmatrix / cp.async helpers (sm_80+, valid on plain sm_100)
// ---------------------------------------------------------------------------
__device__ __forceinline__ void ldsm4(uint32_t& r0, uint32_t& r1, uint32_t& r2,
                                      uint32_t& r3, const void* p) {
    uint32_t a = (uint32_t)__cvta_generic_to_shared(p);
    asm volatile("ldmatrix.sync.aligned.m8n8.x4.shared.b16 {%0,%1,%2,%3}, [%4];"
                 : "=r"(r0), "=r"(r1), "=r"(r2), "=r"(r3) : "r"(a));
}
__device__ __forceinline__ void ldsm4t(uint32_t& r0, uint32_t& r1, uint32_t& r2,
                                       uint32_t& r3, const void* p) {
    uint32_t a = (uint32_t)__cvta_generic_to_shared(p);
    asm volatile("ldmatrix.sync.aligned.m8n8.x4.trans.shared.b16 {%0,%1,%2,%3}, [%4];"
                 : "=r"(r0), "=r"(r1), "=r"(r2), "=r"(r3) : "r"(a));
}
__device__ __forceinline__ void mma_f16(float* c, const uint32_t* a,
                                        uint32_t b0, uint32_t b1) {
    asm volatile(
        "mma.sync.aligned.m16n8k16.row.col.f32.f16.f16.f32 "
        "{%0,%1,%2,%3}, {%4,%5,%6,%7}, {%8,%9}, {%0,%1,%2,%3};"
        : "+f"(c[0]), "+f"(c[1]), "+f"(c[2]), "+f"(c[3])
        : "r"(a[0]), "r"(a[1]), "r"(a[2]), "r"(a[3]), "r"(b0), "r"(b1));
}
__device__ __forceinline__ void cp16(void* s, const void* g) {
    uint32_t sa = (uint32_t)__cvta_generic_to_shared(s);
    asm volatile("cp.async.cg.shared.global [%0], [%1], 16;" :: "r"(sa), "l"(g));
}
__device__ __forceinline__ void cp16z(void* s, const void* g, int sz) {
    uint32_t sa = (uint32_t)__cvta_generic_to_shared(s);
    asm volatile("cp.async.cg.shared.global [%0], [%1], 16, %2;"
                 :: "r"(sa), "l"(g), "r"(sz));
}
#define CP_COMMIT() asm volatile("cp.async.commit_group;" ::: "memory")
#define CP_WAIT2()  asm volatile("cp.async.wait_group 2;" ::: "memory")

// ---------------------------------------------------------------------------
// Kernel P0: w_neigh + adjacency bitmask
// ---------------------------------------------------------------------------
__global__ void prep_kernel(const float* __restrict__ W,
                            const float* __restrict__ a_neigh,
                            const int*   __restrict__ A) {
    int t = blockIdx.x * blockDim.x + threadIdx.x;
    int stride = gridDim.x * blockDim.x;
    for (int idx = t; idx < Hh * Fin; idx += stride) {
        int h = idx / Fin, f = idx % Fin;
        const float* wp = W + ((size_t)h * Fin + f) * Fout;
        const float* ap = a_neigh + h * Fout;
        float s = 0.f;
        for (int d = 0; d < Fout; d++) s += wp[d] * ap[d];
        g_wneigh[idx] = s;
    }
    for (int idx = t; idx < Nn * MW; idx += stride) {
        int i = idx / MW, c = idx % MW;
        unsigned m = 0u;
        for (int bb = 0; bb < 32; bb++) {
            int j = c * 32 + bb;
            if (j < Nn && A[i * Nn + j] != 0) m |= (1u << bb);
        }
        g_mbits[idx] = m;
    }
}

// ---------------------------------------------------------------------------
// Kernel P1: e_neigh[b,h,n] = X[b,n,:] . w_neigh[h,:]  (fp32 exact, feeds exp)
// ---------------------------------------------------------------------------
__global__ void __launch_bounds__(256) eneigh_kernel(const float* __restrict__ X) {
    __shared__ float ws[Hh * Fin];
    const int tid = threadIdx.x;
    for (int i = tid; i < Hh * Fin; i += 256) ws[i] = g_wneigh[i];
    __syncthreads();

    const int warp = tid >> 5, lane = tid & 31;
    const int row = blockIdx.x * 8 + warp;
    const float* xp = X + (size_t)row * Fin;
    float x[8];
    #pragma unroll
    for (int k = 0; k < 8; k++) x[k] = xp[lane + 32 * k];

    const int b = row / Nn, n = row % Nn;
    #pragma unroll
    for (int h = 0; h < Hh; h++) {
        float s = 0.f;
        #pragma unroll
        for (int k = 0; k < 8; k++) s = fmaf(x[k], ws[h * Fin + lane + 32 * k], s);
        #pragma unroll
        for (int o = 16; o > 0; o >>= 1) s += __shfl_xor_sync(0xffffffffu, s, o);
        if (lane == 0) g_eneigh[(size_t)(b * Hh + h) * Nn + n] = s;
    }
}

// ---------------------------------------------------------------------------
// Kernel S0: X -> fp16. One thread per 4 floats.
// ---------------------------------------------------------------------------
__global__ void __launch_bounds__(256) split_x_kernel(const float* __restrict__ X) {
    const int idx = blockIdx.x * 256 + threadIdx.x;   // < BN*64
    const float4 x = ((const float4*)X)[idx];
    __half2 h0 = __floats2half2_rn(x.x, x.y);
    __half2 h1 = __floats2half2_rn(x.z, x.w);
    __half2* d0 = (__half2*)&g_Xs[(size_t)idx * 4];
    d0[0] = h0; d0[1] = h1;
}

// ---------------------------------------------------------------------------
// Kernel S1: W^T -> fp16: g_Wt[col][f] = fp16(W[h][f][d]), col = h*256+d
// ---------------------------------------------------------------------------
__global__ void __launch_bounds__(256) split_w_kernel(const float* __restrict__ W) {
    const int idx = blockIdx.x * 256 + threadIdx.x;   // < HF*64
    const int col = idx >> 6, f4 = idx & 63;
    const int h = col >> 8, d = col & 255;
    #pragma unroll
    for (int i = 0; i < 4; i++) {
        int f = f4 * 4 + i;
        float v = W[((size_t)h * Fin + f) * Fout + d];
        g_Wt[(size_t)col * KS + f] = __float2half_rn(v);
    }
}

// ---------------------------------------------------------------------------
// Kernel G1 (mma.sync + cp.async 4-stage): feats = fp16(X) @ fp16(W'), K=256.
// Epilogue writes fp16 feats for the attention stage.
// Grid: (16 n-tiles, 398 m-tiles) — consecutive CTAs share the A tile in L2.
// ---------------------------------------------------------------------------
__global__ void __launch_bounds__(256, 2) gemm1_mma() {
    extern __shared__ char gsm[];
    __half* As = (__half*)gsm;                              // [GSTG*128][LDS]
    __half* Bs = (__half*)(gsm + (size_t)GSTG * 128 * LDS * 2);

    const int tid  = threadIdx.x;
    const int lane = tid & 31, warp = tid >> 5;
    const int wm = warp >> 2, wn = warp & 3;          // warp grid 2x4
    const int m0 = blockIdx.y * 128, n0 = blockIdx.x * 128;

    const __half* Ag = g_Xs + (size_t)m0 * KS;
    const __half* Bg = g_Wt + (size_t)n0 * KS;

    // loader: 512 16B-vectors per tile per matrix; 2 per thread
    const int lrow0 = tid >> 2, lc16 = tid & 3;
    const int lrow1 = (tid + 256) >> 2;

    #define G1_ISSUE(c) do {                                                     \
        const int _st = (c) & 3, _ko = (c) * KCH;                                \
        cp16(As + (size_t)(_st * 128 + lrow0) * LDS + lc16 * 8,                  \
             Ag + (size_t)lrow0 * KS + _ko + lc16 * 8);                          \
        cp16(As + (size_t)(_st * 128 + lrow1) * LDS + lc16 * 8,                  \
             Ag + (size_t)lrow1 * KS + _ko + lc16 * 8);                          \
        cp16(Bs + (size_t)(_st * 128 + lrow0) * LDS + lc16 * 8,                  \
             Bg + (size_t)lrow0 * KS + _ko + lc16 * 8);                          \
        cp16(Bs + (size_t)(_st * 128 + lrow1) * LDS + lc16 * 8,                  \
             Bg + (size_t)lrow1 * KS + _ko + lc16 * 8);                          \
    } while (0)

    G1_ISSUE(0); CP_COMMIT();
    G1_ISSUE(1); CP_COMMIT();
    G1_ISSUE(2); CP_COMMIT();

    float acc[4][4][4];
    #pragma unroll
    for (int i = 0; i < 4; i++)
        #pragma unroll
        for (int j = 0; j < 4; j++)
            #pragma unroll
            for (int q = 0; q < 4; q++) acc[i][j][q] = 0.f;

    for (int c = 0; c < NKC; c++) {
        CP_WAIT2();               // stage c landed (in this thread)
        __syncthreads();          // visible to all; all warps done with mma(c-1)
        if (c + 3 < NKC) G1_ISSUE(c + 3);
        CP_COMMIT();              // uniform group count (empty at tail)

        const int sb = (c & 3) * 128;
        #pragma unroll
        for (int ks = 0; ks < 2; ks++) {
            uint32_t ra[4][4], rb[2][4];
            #pragma unroll
            for (int am = 0; am < 4; am++)
                ldsm4(ra[am][0], ra[am][1], ra[am][2], ra[am][3],
                      As + (size_t)(sb + wm * 64 + am * 16 + (lane & 15)) * LDS
                         + ks * 16 + (lane >> 4) * 8);
            #pragma unroll
            for (int bn = 0; bn < 2; bn++)
                ldsm4(rb[bn][0], rb[bn][1], rb[bn][2], rb[bn][3],
                      Bs + (size_t)(sb + wn * 32 + bn * 16 + (lane & 7)
                                    + ((lane >> 4) << 3)) * LDS
                         + ks * 16 + ((lane >> 3) & 1) * 8);
            #pragma unroll
            for (int am = 0; am < 4; am++)
                #pragma unroll
                for (int an = 0; an < 4; an++)
                    mma_f16(acc[am][an], ra[am],
                            rb[an >> 1][(an & 1) * 2], rb[an >> 1][(an & 1) * 2 + 1]);
        }
    }

    // epilogue: fp32 -> fp16 feats
    #pragma unroll
    for (int am = 0; am < 4; am++) {
        const int row = m0 + wm * 64 + am * 16 + (lane >> 2);
        #pragma unroll
        for (int an = 0; an < 4; an++) {
            const int col = n0 + wn * 32 + an * 8 + (lane & 3) * 2;
            #pragma unroll
            for (int rr = 0; rr < 2; rr++) {
                const size_t off = (size_t)(row + rr * 8) * HF + col;
                *(__half2*)(g_fhi + off) =
                    __floats2half2_rn(acc[am][an][rr * 2], acc[am][an][rr * 2 + 1]);
            }
        }
    }
}

// ---------------------------------------------------------------------------
// Kernel A2 (mma.sync + cp.async): masked softmax + P@V.
// P = fp16(u_j) exactly; S_i summed from the SAME fp16 values -> exactly
// normalized weights. V = fp16 feats, single segment. K = 208.
// Grid: (2 i-tiles, 4096 bh) — the pair sharing a V slice runs adjacently.
// ---------------------------------------------------------------------------
__global__ void __launch_bounds__(256) attn_mma(const float* __restrict__ bias,
                                                float* __restrict__ out) {
    extern __shared__ char sm[];
    __half*   Ph   = (__half*)(sm + OF_PH);     // [128][LDPH]
    __half*   Vs   = (__half*)(sm + OF_VS);     // [VSTG][16][LDV]
    __half*   uh   = (__half*)(sm + OF_UH);     // [NJP]
    float*    Sinv = (float*)(sm + OF_SI);      // [128]
    float*    red  = (float*)(sm + OF_RED);     // [32]
    unsigned* mb   = (unsigned*)(sm + OF_MB);   // [Nn*MW]

    const int tid = threadIdx.x, lane = tid & 31, warp = tid >> 5;
    const int bh = blockIdx.y, b = bh >> 3, h = bh & 7;
    const int i0 = blockIdx.x * 128;
    const int wm = warp >> 2, wn = warp & 3;    // warp grid 2x4 (64i x 64d)

    const __half* fbh = g_fhi + (size_t)b * Nn * HF + h * Fout;

    // V stage loader: stage = step&3
    #define AT_ISSUE(stp) do {                                                   \
        const int _st = (stp) & 3;                                               \
        _Pragma("unroll")                                                        \
        for (int _q = 0; _q < 2; _q++) {                                         \
            int _v = tid + _q * 256, _row = _v >> 5, _c16 = _v & 31;             \
            int _j = (stp) * 16 + _row;                                          \
            int _sz = (_j < Nn) ? 16 : 0;                                        \
            const __half* _g = fbh + (size_t)(_j < Nn ? _j : 0) * HF + _c16 * 8; \
            cp16z(Vs + (size_t)(_st * 16 + _row) * LDV + _c16 * 8, _g, _sz);     \
        }                                                                        \
    } while (0)

    // prologue V loads overlap softmax/P-build below
    AT_ISSUE(0); CP_COMMIT();
    AT_ISSUE(1); CP_COMMIT();
    AT_ISSUE(2); CP_COMMIT();

    for (int i = tid; i < Nn * MW; i += 256) mb[i] = g_mbits[i];

    // softmax weights: u_j = exp(e_j - gmax), quantized to fp16
    const float* ep = g_eneigh + (size_t)bh * Nn;
    float e = (tid < Nn) ? ep[tid] : -1e30f;
    float m = e;
    #pragma unroll
    for (int o = 16; o > 0; o >>= 1) m = fmaxf(m, __shfl_xor_sync(0xffffffffu, m, o));
    if (lane == 0) red[warp] = m;
    __syncthreads();
    if (tid == 0) {
        float mm = red[0];
        for (int w = 1; w < 8; w++) mm = fmaxf(mm, red[w]);
        red[0] = mm;
    }
    __syncthreads();
    const float gmax = red[0];
    if (tid < NJP)
        uh[tid] = (tid < Nn) ? __float2half_rn(__expf(e - gmax)) : __half(0.f);
    __syncthreads();

    // build P tile (fp16, masked) + row sums from the SAME quantized values
    for (int t = tid; t < 128 * NPR; t += 256) {
        const int i = t / NPR, jp = t - i * NPR;
        const int ig = i0 + i;
        uint32_t mw_ = 0u;
        if (ig < Nn) {
            const unsigned* mrow = mb + ig * MW;
            const int j0 = jp * 2, j1 = j0 + 1;
            if ((mrow[j0 >> 5] >> (j0 & 31)) & 1u) mw_ |= 0x0000FFFFu;
            if ((mrow[j1 >> 5] >> (j1 & 31)) & 1u) mw_ |= 0xFFFF0000u;
        }
        const uint32_t uhp = ((const uint32_t*)uh)[jp];
        ((uint32_t*)(Ph + (size_t)i * LDPH))[jp] = uhp & mw_;
    }
    for (int il = warp; il < 128; il += 8) {
        const int ig = i0 + il;
        float s = 0.f;
        if (ig < Nn) {
            const unsigned* mrow = mb + ig * MW;
            for (int j = lane; j < Nn; j += 32)
                if (mrow[j >> 5] & (1u << (j & 31))) s += __half2float(uh[j]);
        }
        #pragma unroll
        for (int o = 16; o > 0; o >>= 1) s += __shfl_xor_sync(0xffffffffu, s, o);
        if (lane == 0) Sinv[il] = (ig < Nn) ? (1.f / s) : 0.f;
    }
    __syncthreads();

    // K-loop: 13 steps of k=16, 4-stage cp.async
    float acc[4][8][4];
    #pragma unroll
    for (int i = 0; i < 4; i++)
        #pragma unroll
        for (int j = 0; j < 8; j++)
            #pragma unroll
            for (int q = 0; q < 4; q++) acc[i][j][q] = 0.f;

    for (int step = 0; step < NSTEP; step++) {
        CP_WAIT2();
        __syncthreads();
        if (step + 3 < NSTEP) AT_ISSUE(step + 3);
        CP_COMMIT();

        const int kc = step * 16;
        const int vb = (step & 3) * 16;

        uint32_t ra[4][4], rb[4][4];
        #pragma unroll
        for (int am = 0; am < 4; am++)
            ldsm4(ra[am][0], ra[am][1], ra[am][2], ra[am][3],
                  Ph + (size_t)(wm * 64 + am * 16 + (lane & 15)) * LDPH
                     + kc + (lane >> 4) * 8);
        #pragma unroll
        for (int q = 0; q < 4; q++)
            ldsm4t(rb[q][0], rb[q][1], rb[q][2], rb[q][3],
                   Vs + (size_t)(vb + (lane & 15)) * LDV
                      + wn * 64 + q * 16 + ((lane >> 4) << 3));
        #pragma unroll
        for (int am = 0; am < 4; am++)
            #pragma unroll
            for (int an = 0; an < 8; an++)
                mma_f16(acc[am][an], ra[am],
                        rb[an >> 1][(an & 1) * 2], rb[an >> 1][(an & 1) * 2 + 1]);
    }

    // epilogue: scale by Sinv, add bias, store fp32
    #pragma unroll
    for (int am = 0; am < 4; am++) {
        const int il = wm * 64 + am * 16 + (lane >> 2);
        const int ig0 = i0 + il, ig1 = ig0 + 8;
        const float si0 = Sinv[il], si1 = Sinv[il + 8];
        #pragma unroll
        for (int an = 0; an < 8; an++) {
            const int d = wn * 64 + an * 8 + (lane & 3) * 2;
            const float bv0 = bias[h * Fout + d];
            const float bv1 = bias[h * Fout + d + 1];
            if (ig0 < Nn) {
                float* p = out + (size_t)(b * Nn + ig0) * HF + h * Fout + d;
                *(float2*)p = make_float2(fmaf(acc[am][an][0], si0, bv0),
                                          fmaf(acc[am][an][1], si0, bv1));
            }
            if (ig1 < Nn) {
                float* p = out + (size_t)(b * Nn + ig1) * HF + h * Fout + d;
                *(float2*)p = make_float2(fmaf(acc[am][an][2], si1, bv0),
                                          fmaf(acc[am][an][3], si1, bv1));
            }
        }
    }
}

// ---------------------------------------------------------------------------
extern "C" void kernel_launch(void* const* d_in, const int* in_sizes, int n_in,
                              void* d_out, int out_size) {
    const float* X       = (const float*)d_in[0];
    const int*   A       = (const int*)  d_in[1];
    const float* W       = (const float*)d_in[2];
    // d_in[3] = a_self: no effect on output (softmax row-constant cancels)
    const float* a_neigh = (const float*)d_in[4];
    const float* bias    = (const float*)d_in[5];
    float* out = (float*)d_out;

    prep_kernel<<<64, 256>>>(W, a_neigh, A);
    eneigh_kernel<<<BN / 8, 256>>>(X);
    split_x_kernel<<<BN * 64 / 256, 256>>>(X);
    split_w_kernel<<<HF * 64 / 256, 256>>>(W);

    cudaFuncSetAttribute(gemm1_mma, cudaFuncAttributeMaxDynamicSharedMemorySize,
                         G1_SMEM);
    gemm1_mma<<<dim3(HF / 128, BN / 128), 256, G1_SMEM>>>();

    cudaFuncSetAttribute(attn_mma, cudaFuncAttributeMaxDynamicSharedMemorySize,
                         ATTN_SMEM);
    attn_mma<<<dim3(2, Bn * Hh), 256, ATTN_SMEM>>>(bias, out);
}